// round 2
// baseline (speedup 1.0000x reference)
#include <cuda_runtime.h>
#include <cuda_bf16.h>
#include <cstdint>
#include <cstddef>

#define DEVI __device__ __forceinline__

namespace {
constexpr int BATCH = 16, SEQ = 512, DIM = 1024, NH = 16, HDIM = 64;
constexpr int MROWS = BATCH * SEQ;      // 8192
constexpr int HALFWIN = 64;
constexpr float ATT_SCALE = 0.125f;     // 1/sqrt(64)
constexpr int BM = 128, BN = 128, BK = 32;
constexpr int SPITCH = 40;              // bf16 elems per smem row (pad 8 -> conflict-free ldmatrix)
}

// ---------------- scratch (device globals; no allocation allowed) ----------------
__device__ __nv_bfloat16 g_hb[MROWS * DIM];
__device__ __nv_bfloat16 g_cb[MROWS * DIM];
__device__ __nv_bfloat16 g_w5[5 * DIM * DIM];   // Wq,Wk,Wv,Wo,Wg packed
__device__ __nv_bfloat16 g_q[MROWS * DIM];
__device__ __nv_bfloat16 g_k[MROWS * DIM];
__device__ __nv_bfloat16 g_v[MROWS * DIM];
__device__ __nv_bfloat16 g_attn[MROWS * DIM];
__device__ float g_gate[MROWS * DIM];
__device__ float g_yo[MROWS * DIM];

// ---------------- small helpers ----------------
DEVI uint32_t pack_bf16(float a, float b) {
    __nv_bfloat162 t;
    t.x = __float2bfloat16(a);
    t.y = __float2bfloat16(b);
    return *reinterpret_cast<uint32_t*>(&t);
}

DEVI void mma16816(float* c, const uint32_t* a, const uint32_t* b) {
    asm volatile(
        "mma.sync.aligned.m16n8k16.row.col.f32.bf16.bf16.f32 "
        "{%0,%1,%2,%3}, {%4,%5,%6,%7}, {%8,%9}, {%0,%1,%2,%3};"
        : "+f"(c[0]), "+f"(c[1]), "+f"(c[2]), "+f"(c[3])
        : "r"(a[0]), "r"(a[1]), "r"(a[2]), "r"(a[3]), "r"(b[0]), "r"(b[1]));
}
DEVI void ldmx4(uint32_t* r, uint32_t addr) {
    asm volatile("ldmatrix.sync.aligned.m8n8.x4.shared.b16 {%0,%1,%2,%3}, [%4];"
                 : "=r"(r[0]), "=r"(r[1]), "=r"(r[2]), "=r"(r[3]) : "r"(addr));
}
DEVI void ldmx2(uint32_t* r, uint32_t addr) {
    asm volatile("ldmatrix.sync.aligned.m8n8.x2.shared.b16 {%0,%1}, [%2];"
                 : "=r"(r[0]), "=r"(r[1]) : "r"(addr));
}
DEVI void ldmx2t(uint32_t* r, uint32_t addr) {
    asm volatile("ldmatrix.sync.aligned.m8n8.x2.trans.shared.b16 {%0,%1}, [%2];"
                 : "=r"(r[0]), "=r"(r[1]) : "r"(addr));
}
DEVI void cpasync16(uint32_t dst, const void* src) {
    asm volatile("cp.async.cg.shared.global [%0], [%1], 16;" :: "r"(dst), "l"(src));
}

// ---------------- fp32 -> bf16 conversion (pair-of-buffers variant) ----------------
__global__ void cvt2_kernel(const float* __restrict__ s0, __nv_bfloat16* __restrict__ d0,
                            const float* __restrict__ s1, __nv_bfloat16* __restrict__ d1,
                            int nvec /* n/4 per buffer */) {
    const int stride = gridDim.x * blockDim.x;
    for (int i = blockIdx.x * blockDim.x + threadIdx.x; i < 2 * nvec; i += stride) {
        const bool second = (i >= nvec);
        const float* src = second ? s1 : s0;
        __nv_bfloat16* dst = second ? d1 : d0;
        const int idx = (second ? i - nvec : i) * 4;
        float4 f = *reinterpret_cast<const float4*>(src + idx);
        __nv_bfloat162 lo, hi;
        lo.x = __float2bfloat16(f.x); lo.y = __float2bfloat16(f.y);
        hi.x = __float2bfloat16(f.z); hi.y = __float2bfloat16(f.w);
        *reinterpret_cast<__nv_bfloat162*>(dst + idx)     = lo;
        *reinterpret_cast<__nv_bfloat162*>(dst + idx + 2) = hi;
    }
}

// converts 5 weight matrices (one per blockIdx.y) into packed g_w5
__global__ void cvtw_kernel(const float* __restrict__ wq, const float* __restrict__ wk,
                            const float* __restrict__ wv, const float* __restrict__ wo,
                            const float* __restrict__ wg) {
    const int which = blockIdx.y;
    const float* src = (which == 0) ? wq : (which == 1) ? wk : (which == 2) ? wv
                     : (which == 3) ? wo : wg;
    __nv_bfloat16* dst = g_w5 + (size_t)which * DIM * DIM;
    const int nvec = DIM * DIM / 4;
    const int stride = gridDim.x * blockDim.x;
    for (int i = blockIdx.x * blockDim.x + threadIdx.x; i < nvec; i += stride) {
        const int idx = i * 4;
        float4 f = *reinterpret_cast<const float4*>(src + idx);
        __nv_bfloat162 lo, hi;
        lo.x = __float2bfloat16(f.x); lo.y = __float2bfloat16(f.y);
        hi.x = __float2bfloat16(f.z); hi.y = __float2bfloat16(f.w);
        *reinterpret_cast<__nv_bfloat162*>(dst + idx)     = lo;
        *reinterpret_cast<__nv_bfloat162*>(dst + idx + 2) = hi;
    }
}

// ---------------- bf16 GEMM: C[M,N] = A[M,K] @ W[N,K]^T + bias ----------------
// M=8192, N=K=1024. 128x128x32 tiles, 256 threads, 8 warps (2m x 4n), warp = 64x32.
template<bool OUT_BF16>
__global__ __launch_bounds__(256)
void gemm_kernel(const __nv_bfloat16* __restrict__ A,
                 const __nv_bfloat16* __restrict__ W,
                 const float* __restrict__ bias,
                 void* __restrict__ Cout) {
    __shared__ __nv_bfloat16 As[2][BM * SPITCH];
    __shared__ __nv_bfloat16 Ws[2][BN * SPITCH];
    const int tid  = threadIdx.x;
    const int lane = tid & 31, wid = tid >> 5;
    const int wm = wid >> 2, wn = wid & 3;
    const int bm = blockIdx.y * BM, bn = blockIdx.x * BN;

    float acc[4][4][4];
#pragma unroll
    for (int mt = 0; mt < 4; mt++)
#pragma unroll
        for (int nt = 0; nt < 4; nt++)
#pragma unroll
            for (int i = 0; i < 4; i++) acc[mt][nt][i] = 0.f;

    auto stage = [&](int kt, int buf) {
#pragma unroll
        for (int s = 0; s < 2; s++) {
            const int c = tid + s * 256;
            const int row = c >> 2, ch = c & 3;
            const __nv_bfloat16* ga = A + (size_t)(bm + row) * DIM + kt * BK + ch * 8;
            cpasync16((uint32_t)__cvta_generic_to_shared(&As[buf][row * SPITCH + ch * 8]), ga);
            const __nv_bfloat16* gw = W + (size_t)(bn + row) * DIM + kt * BK + ch * 8;
            cpasync16((uint32_t)__cvta_generic_to_shared(&Ws[buf][row * SPITCH + ch * 8]), gw);
        }
        asm volatile("cp.async.commit_group;" ::: "memory");
    };

    stage(0, 0);
    constexpr int KT = DIM / BK;  // 32
    for (int kt = 0; kt < KT; kt++) {
        const int buf = kt & 1;
        asm volatile("cp.async.wait_group 0;" ::: "memory");
        __syncthreads();
        if (kt + 1 < KT) stage(kt + 1, buf ^ 1);
#pragma unroll
        for (int ks = 0; ks < 2; ks++) {
            uint32_t af[4][4], bf[4][2];
#pragma unroll
            for (int mt = 0; mt < 4; mt++) {
                const int row = wm * 64 + mt * 16 + (lane & 15);
                ldmx4(af[mt], (uint32_t)__cvta_generic_to_shared(
                    &As[buf][row * SPITCH + ks * 16 + (lane >> 4) * 8]));
            }
#pragma unroll
            for (int nt = 0; nt < 4; nt++) {
                const int row = wn * 32 + nt * 8 + (lane & 7);
                ldmx2(bf[nt], (uint32_t)__cvta_generic_to_shared(
                    &Ws[buf][row * SPITCH + ks * 16 + ((lane >> 3) & 1) * 8]));
            }
#pragma unroll
            for (int mt = 0; mt < 4; mt++)
#pragma unroll
                for (int nt = 0; nt < 4; nt++)
                    mma16816(acc[mt][nt], af[mt], bf[nt]);
        }
    }

    float* fC = reinterpret_cast<float*>(Cout);
    __nv_bfloat16* bC = reinterpret_cast<__nv_bfloat16*>(Cout);
#pragma unroll
    for (int mt = 0; mt < 4; mt++) {
        const int row0 = bm + wm * 64 + mt * 16 + (lane >> 2);
#pragma unroll
        for (int nt = 0; nt < 4; nt++) {
            const int col = bn + wn * 32 + nt * 8 + (lane & 3) * 2;
            const float b0 = bias[col], b1 = bias[col + 1];
            const float x0 = acc[mt][nt][0] + b0;
            const float x1 = acc[mt][nt][1] + b1;
            const float x2 = acc[mt][nt][2] + b0;
            const float x3 = acc[mt][nt][3] + b1;
            if (OUT_BF16) {
                *reinterpret_cast<uint32_t*>(bC + (size_t)row0 * DIM + col)       = pack_bf16(x0, x1);
                *reinterpret_cast<uint32_t*>(bC + (size_t)(row0 + 8) * DIM + col) = pack_bf16(x2, x3);
            } else {
                *reinterpret_cast<float2*>(fC + (size_t)row0 * DIM + col)       = make_float2(x0, x1);
                *reinterpret_cast<float2*>(fC + (size_t)(row0 + 8) * DIM + col) = make_float2(x2, x3);
            }
        }
    }
}

// ---------------- banded attention ----------------
// block = (b*16+h, qtile of 64 queries), 128 threads (4 warps x 16 query rows).
// Keys needed: [qt*64-64, qt*64+128) -> 192 rows. K/V staged bf16, XOR-swizzled, 48KB.
__global__ __launch_bounds__(128)
void attn_kernel(const __nv_bfloat16* __restrict__ Q,
                 const __nv_bfloat16* __restrict__ K,
                 const __nv_bfloat16* __restrict__ V,
                 __nv_bfloat16* __restrict__ Out) {
    extern __shared__ char smem[];
    char* Ks = smem;             // 192 rows * 128B
    char* Vs = smem + 24576;     // 192 rows * 128B
    const int b = blockIdx.x >> 4, h = blockIdx.x & 15;
    const int qt = blockIdx.y;
    const int tid = threadIdx.x, lane = tid & 31, wid = tid >> 5;
    const int k0 = qt * 64 - 64;
    const size_t base = ((size_t)b * SEQ) * DIM + h * HDIM;

    // stage K,V band (zero-fill out-of-range)
    for (int c = tid; c < 192 * 8; c += 128) {
        const int row = c >> 3, ch = c & 7;
        const int j = k0 + row;
        uint4 kv = make_uint4(0u, 0u, 0u, 0u), vv = make_uint4(0u, 0u, 0u, 0u);
        if (j >= 0 && j < SEQ) {
            kv = reinterpret_cast<const uint4*>(K + base + (size_t)j * DIM)[ch];
            vv = reinterpret_cast<const uint4*>(V + base + (size_t)j * DIM)[ch];
        }
        const int sw = ch ^ (row & 7);
        *reinterpret_cast<uint4*>(Ks + row * 128 + sw * 16) = kv;
        *reinterpret_cast<uint4*>(Vs + row * 128 + sw * 16) = vv;
    }
    __syncthreads();

    // Q A-fragments directly from global (frag layout == 2 contiguous bf16)
    uint32_t qf[4][4];
    const int qr = qt * 64 + wid * 16 + (lane >> 2);  // covers rows qr and qr+8
    {
        const __nv_bfloat16* q0 = Q + base + (size_t)qr * DIM;
        const __nv_bfloat16* q8 = Q + base + (size_t)(qr + 8) * DIM;
#pragma unroll
        for (int kt = 0; kt < 4; kt++) {
            const int c0 = kt * 16 + (lane & 3) * 2;
            qf[kt][0] = *reinterpret_cast<const uint32_t*>(q0 + c0);
            qf[kt][1] = *reinterpret_cast<const uint32_t*>(q8 + c0);
            qf[kt][2] = *reinterpret_cast<const uint32_t*>(q0 + c0 + 8);
            qf[kt][3] = *reinterpret_cast<const uint32_t*>(q8 + c0 + 8);
        }
    }

    // S = Q @ K^T : 24 n-tiles of 8 keys, 4 k-tiles of 16 dims
    float sc[24][4];
#pragma unroll
    for (int nt = 0; nt < 24; nt++)
#pragma unroll
        for (int i = 0; i < 4; i++) sc[nt][i] = 0.f;
#pragma unroll
    for (int kt = 0; kt < 4; kt++) {
#pragma unroll
        for (int nt = 0; nt < 24; nt++) {
            uint32_t kb[2];
            const int krow = nt * 8 + (lane & 7);
            const int ch = kt * 2 + ((lane >> 3) & 1);
            ldmx2(kb, (uint32_t)__cvta_generic_to_shared(Ks + krow * 128 + (ch ^ (krow & 7)) * 16));
            mma16816(sc[nt], qf[kt], kb);
        }
    }

    // mask + softmax (rows qr, qr+8; 4-lane row groups)
    float mx0 = -1e30f, mx1 = -1e30f;
#pragma unroll
    for (int nt = 0; nt < 24; nt++) {
#pragma unroll
        for (int c = 0; c < 2; c++) {
            const int kj = k0 + nt * 8 + (lane & 3) * 2 + c;
            const bool inr = (kj >= 0) && (kj < SEQ);
            int d0 = qr - kj;     if (d0 < 0) d0 = -d0;
            int d1 = qr + 8 - kj; if (d1 < 0) d1 = -d1;
            const float s0 = (inr && d0 <= HALFWIN) ? sc[nt][c] * ATT_SCALE : -1e30f;
            const float s1 = (inr && d1 <= HALFWIN) ? sc[nt][c + 2] * ATT_SCALE : -1e30f;
            sc[nt][c] = s0; sc[nt][c + 2] = s1;
            mx0 = fmaxf(mx0, s0); mx1 = fmaxf(mx1, s1);
        }
    }
    mx0 = fmaxf(mx0, __shfl_xor_sync(0xffffffffu, mx0, 1));
    mx0 = fmaxf(mx0, __shfl_xor_sync(0xffffffffu, mx0, 2));
    mx1 = fmaxf(mx1, __shfl_xor_sync(0xffffffffu, mx1, 1));
    mx1 = fmaxf(mx1, __shfl_xor_sync(0xffffffffu, mx1, 2));
    float l0 = 0.f, l1 = 0.f;
#pragma unroll
    for (int nt = 0; nt < 24; nt++) {
#pragma unroll
        for (int c = 0; c < 2; c++) {
            const float p0 = __expf(sc[nt][c] - mx0);
            const float p1 = __expf(sc[nt][c + 2] - mx1);
            sc[nt][c] = p0; sc[nt][c + 2] = p1;
            l0 += p0; l1 += p1;
        }
    }
    l0 += __shfl_xor_sync(0xffffffffu, l0, 1);
    l0 += __shfl_xor_sync(0xffffffffu, l0, 2);
    l1 += __shfl_xor_sync(0xffffffffu, l1, 1);
    l1 += __shfl_xor_sync(0xffffffffu, l1, 2);

    // O = P @ V : reuse P (C-frag layout == A-frag layout), V via ldmatrix.trans
    float oacc[8][4];
#pragma unroll
    for (int dt = 0; dt < 8; dt++)
#pragma unroll
        for (int i = 0; i < 4; i++) oacc[dt][i] = 0.f;
#pragma unroll
    for (int jt = 0; jt < 12; jt++) {
        uint32_t pa[4];
        pa[0] = pack_bf16(sc[2 * jt][0], sc[2 * jt][1]);
        pa[1] = pack_bf16(sc[2 * jt][2], sc[2 * jt][3]);
        pa[2] = pack_bf16(sc[2 * jt + 1][0], sc[2 * jt + 1][1]);
        pa[3] = pack_bf16(sc[2 * jt + 1][2], sc[2 * jt + 1][3]);
        const int vrow = jt * 16 + (lane & 15);
#pragma unroll
        for (int dt = 0; dt < 8; dt++) {
            uint32_t vb[2];
            ldmx2t(vb, (uint32_t)__cvta_generic_to_shared(Vs + vrow * 128 + (dt ^ (vrow & 7)) * 16));
            mma16816(oacc[dt], pa, vb);
        }
    }

    const float i0 = 1.f / l0, i1 = 1.f / l1;
    __nv_bfloat16* ob = Out + base;
#pragma unroll
    for (int dt = 0; dt < 8; dt++) {
        const int col = dt * 8 + (lane & 3) * 2;
        *reinterpret_cast<uint32_t*>(ob + (size_t)qr * DIM + col) =
            pack_bf16(oacc[dt][0] * i0, oacc[dt][1] * i0);
        *reinterpret_cast<uint32_t*>(ob + (size_t)(qr + 8) * DIM + col) =
            pack_bf16(oacc[dt][2] * i1, oacc[dt][3] * i1);
    }
}

// ---------------- fused gate * attn, blend, LayerNorm ----------------
__global__ __launch_bounds__(256)
void final_kernel(const float* __restrict__ hid, const float* __restrict__ gate,
                  const float* __restrict__ yo, const float* __restrict__ gamma,
                  const float* __restrict__ beta, float* __restrict__ out) {
    const int row = blockIdx.x;
    const int tid = threadIdx.x;
    const size_t off = (size_t)row * DIM + tid * 4;
    const float4 hv = *reinterpret_cast<const float4*>(hid + off);
    const float4 gv = *reinterpret_cast<const float4*>(gate + off);
    const float4 yv = *reinterpret_cast<const float4*>(yo + off);
    float y[4];
    y[0] = 0.5f * hv.x + 0.5f * yv.x / (1.f + __expf(-gv.x));
    y[1] = 0.5f * hv.y + 0.5f * yv.y / (1.f + __expf(-gv.y));
    y[2] = 0.5f * hv.z + 0.5f * yv.z / (1.f + __expf(-gv.z));
    y[3] = 0.5f * hv.w + 0.5f * yv.w / (1.f + __expf(-gv.w));
    float s = y[0] + y[1] + y[2] + y[3];
    float s2 = y[0] * y[0] + y[1] * y[1] + y[2] * y[2] + y[3] * y[3];
#pragma unroll
    for (int o = 16; o > 0; o >>= 1) {
        s  += __shfl_xor_sync(0xffffffffu, s, o);
        s2 += __shfl_xor_sync(0xffffffffu, s2, o);
    }
    __shared__ float rs[8], rs2[8];
    if ((tid & 31) == 0) { rs[tid >> 5] = s; rs2[tid >> 5] = s2; }
    __syncthreads();
    float ts = 0.f, ts2 = 0.f;
#pragma unroll
    for (int w = 0; w < 8; w++) { ts += rs[w]; ts2 += rs2[w]; }
    const float mean = ts * (1.f / DIM);
    const float var = ts2 * (1.f / DIM) - mean * mean;
    const float rstd = rsqrtf(var + 1e-5f);
    const float4 gm = *reinterpret_cast<const float4*>(gamma + tid * 4);
    const float4 bt = *reinterpret_cast<const float4*>(beta + tid * 4);
    float4 o4;
    o4.x = (y[0] - mean) * rstd * gm.x + bt.x;
    o4.y = (y[1] - mean) * rstd * gm.y + bt.y;
    o4.z = (y[2] - mean) * rstd * gm.z + bt.z;
    o4.w = (y[3] - mean) * rstd * gm.w + bt.w;
    *reinterpret_cast<float4*>(out + off) = o4;
}

// ---------------- launch ----------------
extern "C" void kernel_launch(void* const* d_in, const int* in_sizes, int n_in,
                              void* d_out, int out_size) {
    (void)in_sizes; (void)n_in; (void)out_size;
    const float* hidden = (const float*)d_in[0];
    const float* cross  = (const float*)d_in[1];
    const float* Wq = (const float*)d_in[2];  const float* bq = (const float*)d_in[3];
    const float* Wk = (const float*)d_in[4];  const float* bk = (const float*)d_in[5];
    const float* Wv = (const float*)d_in[6];  const float* bv = (const float*)d_in[7];
    const float* Wo = (const float*)d_in[8];  const float* bo = (const float*)d_in[9];
    const float* Wg = (const float*)d_in[10]; const float* bg = (const float*)d_in[11];
    const float* gamma = (const float*)d_in[12];
    const float* beta  = (const float*)d_in[13];

    __nv_bfloat16 *hb, *cb, *w5, *q, *k, *v, *at;
    float *gate, *yo;
    cudaGetSymbolAddress((void**)&hb, g_hb);
    cudaGetSymbolAddress((void**)&cb, g_cb);
    cudaGetSymbolAddress((void**)&w5, g_w5);
    cudaGetSymbolAddress((void**)&q,  g_q);
    cudaGetSymbolAddress((void**)&k,  g_k);
    cudaGetSymbolAddress((void**)&v,  g_v);
    cudaGetSymbolAddress((void**)&at, g_attn);
    cudaGetSymbolAddress((void**)&gate, g_gate);
    cudaGetSymbolAddress((void**)&yo,   g_yo);

    const int nXDvec = MROWS * DIM / 4;   // 2.10M float4 per activation
    cvt2_kernel<<<1024, 256>>>(hidden, hb, cross, cb, nXDvec);
    cvtw_kernel<<<dim3(128, 5), 256>>>(Wq, Wk, Wv, Wo, Wg);

    const __nv_bfloat16* wq = w5;
    const __nv_bfloat16* wk = w5 + 1 * (size_t)DIM * DIM;
    const __nv_bfloat16* wv = w5 + 2 * (size_t)DIM * DIM;
    const __nv_bfloat16* wo = w5 + 3 * (size_t)DIM * DIM;
    const __nv_bfloat16* wg = w5 + 4 * (size_t)DIM * DIM;

    dim3 gg(DIM / BN, MROWS / BM);  // (8, 64)
    gemm_kernel<true ><<<gg, 256>>>(hb, wq, bq, q);
    gemm_kernel<true ><<<gg, 256>>>(cb, wk, bk, k);
    gemm_kernel<true ><<<gg, 256>>>(cb, wv, bv, v);
    gemm_kernel<false><<<gg, 256>>>(hb, wg, bg, gate);

    attn_kernel<<<dim3(BATCH * NH, SEQ / 64), 128, 49152>>>(q, k, v, at);

    gemm_kernel<false><<<gg, 256>>>(at, wo, bo, yo);

    final_kernel<<<MROWS, 256>>>(hidden, gate, yo, gamma, beta, (float*)d_out);
}

// round 7
// speedup vs baseline: 1.2717x; 1.2717x over previous
#include <cuda_runtime.h>
#include <cuda_bf16.h>
#include <cstdint>
#include <cstddef>

#define DEVI __device__ __forceinline__

namespace {
constexpr int BATCH = 16, SEQ = 512, DIM = 1024, NH = 16, HDIM = 64;
constexpr int MROWS = BATCH * SEQ;      // 8192
constexpr int HALFWIN = 64;
constexpr float ATT_SCALE = 0.125f;     // 1/sqrt(64)
constexpr int BM = 128, BN = 128, BK = 64;   // K-chunk = 64 bf16 = 128B row (XOR swizzle)
constexpr int KT = DIM / BK;                 // 16
constexpr int NST = 3;
constexpr int STAGE_BYTES = (BM + BN) * 128; // 32768 (A 16KB + B 16KB)
constexpr int GEMM_SMEM = NST * STAGE_BYTES + 256;  // + align slack
}

// ---------------- scratch (device globals; no allocation allowed) ----------------
__device__ __nv_bfloat16 g_hb[MROWS * DIM];
__device__ __nv_bfloat16 g_cb[MROWS * DIM];
__device__ __nv_bfloat16 g_w5[5 * DIM * DIM];   // Wq,Wk,Wv,Wo,Wg packed
__device__ __nv_bfloat16 g_q[MROWS * DIM];
__device__ __nv_bfloat16 g_k[MROWS * DIM];
__device__ __nv_bfloat16 g_v[MROWS * DIM];
__device__ __nv_bfloat16 g_attn[MROWS * DIM];
__device__ float g_gate[MROWS * DIM];
__device__ float g_yo[MROWS * DIM];

// ---------------- small helpers ----------------
DEVI uint32_t pack_bf16(float a, float b) {
    __nv_bfloat162 t;
    t.x = __float2bfloat16(a);
    t.y = __float2bfloat16(b);
    return *reinterpret_cast<uint32_t*>(&t);
}
DEVI void mma16816(float* c, const uint32_t* a, const uint32_t* b) {
    asm volatile(
        "mma.sync.aligned.m16n8k16.row.col.f32.bf16.bf16.f32 "
        "{%0,%1,%2,%3}, {%4,%5,%6,%7}, {%8,%9}, {%0,%1,%2,%3};"
        : "+f"(c[0]), "+f"(c[1]), "+f"(c[2]), "+f"(c[3])
        : "r"(a[0]), "r"(a[1]), "r"(a[2]), "r"(a[3]), "r"(b[0]), "r"(b[1]));
}
DEVI void ldmx4(uint32_t* r, uint32_t addr) {
    asm volatile("ldmatrix.sync.aligned.m8n8.x4.shared.b16 {%0,%1,%2,%3}, [%4];"
                 : "=r"(r[0]), "=r"(r[1]), "=r"(r[2]), "=r"(r[3]) : "r"(addr));
}
DEVI void ldmx2(uint32_t* r, uint32_t addr) {
    asm volatile("ldmatrix.sync.aligned.m8n8.x2.shared.b16 {%0,%1}, [%2];"
                 : "=r"(r[0]), "=r"(r[1]) : "r"(addr));
}
DEVI void ldmx2t(uint32_t* r, uint32_t addr) {
    asm volatile("ldmatrix.sync.aligned.m8n8.x2.trans.shared.b16 {%0,%1}, [%2];"
                 : "=r"(r[0]), "=r"(r[1]) : "r"(addr));
}
DEVI void cpasync16(uint32_t dst, const void* src) {
    asm volatile("cp.async.cg.shared.global [%0], [%1], 16;" :: "r"(dst), "l"(src));
}

// ---------------- fp32 -> bf16 conversions ----------------
__global__ void cvt2_kernel(const float* __restrict__ s0, __nv_bfloat16* __restrict__ d0,
                            const float* __restrict__ s1, __nv_bfloat16* __restrict__ d1,
                            int nvec) {
    const int stride = gridDim.x * blockDim.x;
    for (int i = blockIdx.x * blockDim.x + threadIdx.x; i < 2 * nvec; i += stride) {
        const bool second = (i >= nvec);
        const float* src = second ? s1 : s0;
        __nv_bfloat16* dst = second ? d1 : d0;
        const int idx = (second ? i - nvec : i) * 4;
        float4 f = *reinterpret_cast<const float4*>(src + idx);
        __nv_bfloat162 lo, hi;
        lo.x = __float2bfloat16(f.x); lo.y = __float2bfloat16(f.y);
        hi.x = __float2bfloat16(f.z); hi.y = __float2bfloat16(f.w);
        *reinterpret_cast<__nv_bfloat162*>(dst + idx)     = lo;
        *reinterpret_cast<__nv_bfloat162*>(dst + idx + 2) = hi;
    }
}
__global__ void cvtw_kernel(const float* __restrict__ wq, const float* __restrict__ wk,
                            const float* __restrict__ wv, const float* __restrict__ wo,
                            const float* __restrict__ wg) {
    const int which = blockIdx.y;
    const float* src = (which == 0) ? wq : (which == 1) ? wk : (which == 2) ? wv
                     : (which == 3) ? wo : wg;
    __nv_bfloat16* dst = g_w5 + (size_t)which * DIM * DIM;
    const int nvec = DIM * DIM / 4;
    const int stride = gridDim.x * blockDim.x;
    for (int i = blockIdx.x * blockDim.x + threadIdx.x; i < nvec; i += stride) {
        const int idx = i * 4;
        float4 f = *reinterpret_cast<const float4*>(src + idx);
        __nv_bfloat162 lo, hi;
        lo.x = __float2bfloat16(f.x); lo.y = __float2bfloat16(f.y);
        hi.x = __float2bfloat16(f.z); hi.y = __float2bfloat16(f.w);
        *reinterpret_cast<__nv_bfloat162*>(dst + idx)     = lo;
        *reinterpret_cast<__nv_bfloat162*>(dst + idx + 2) = hi;
    }
}

// ---------------- bf16 GEMM: C[M,N] = A[M,K] @ W[N,K]^T + bias ----------------
// 128x128x64 tiles, 3-stage cp.async pipeline, XOR-swizzled 128B rows, 8 warps (2m x 4n).
template<bool OUT_BF16>
__global__ __launch_bounds__(256, 2)
void gemm_kernel(const __nv_bfloat16* __restrict__ A,
                 const __nv_bfloat16* __restrict__ W,
                 const float* __restrict__ bias,
                 void* __restrict__ Cout) {
    extern __shared__ char dsm[];
    const uint32_t sb = ((uint32_t)__cvta_generic_to_shared(dsm) + 127) & ~127u;
    const int tid  = threadIdx.x;
    const int lane = tid & 31, wid = tid >> 5;
    const int wm = wid >> 2, wn = wid & 3;
    const int bm = blockIdx.y * BM, bn = blockIdx.x * BN;

    float acc[4][4][4];
#pragma unroll
    for (int mt = 0; mt < 4; mt++)
#pragma unroll
        for (int nt = 0; nt < 4; nt++)
#pragma unroll
            for (int i = 0; i < 4; i++) acc[mt][nt][i] = 0.f;

    auto stage = [&](int kt) {
        const uint32_t abase = sb + (kt % NST) * STAGE_BYTES;
        const uint32_t bbase = abase + BM * 128;
#pragma unroll
        for (int s = 0; s < 4; s++) {                     // 1024 A-chunks / 256 thr
            const int i = tid + s * 256;
            const int r = i >> 3, c = i & 7;
            cpasync16(abase + r * 128 + ((c ^ (r & 7)) * 16),
                      A + (size_t)(bm + r) * DIM + kt * BK + c * 8);
        }
#pragma unroll
        for (int s = 0; s < 4; s++) {                     // 1024 B-chunks / 256 thr
            const int i = tid + s * 256;
            const int r = i >> 3, c = i & 7;
            cpasync16(bbase + r * 128 + ((c ^ (r & 7)) * 16),
                      W + (size_t)(bn + r) * DIM + kt * BK + c * 8);
        }
        asm volatile("cp.async.commit_group;" ::: "memory");
    };

    stage(0);
    stage(1);
    for (int kt = 0; kt < KT; kt++) {
        if (kt < KT - 1) asm volatile("cp.async.wait_group 1;" ::: "memory");
        else             asm volatile("cp.async.wait_group 0;" ::: "memory");
        __syncthreads();                                  // stage kt visible; prev compute done
        if (kt + 2 < KT) stage(kt + 2);
        const uint32_t abase = sb + (kt % NST) * STAGE_BYTES;
        const uint32_t bbase = abase + BM * 128;
#pragma unroll
        for (int ks = 0; ks < BK / 16; ks++) {
            uint32_t af[4][4], bf[4][2];
#pragma unroll
            for (int mt = 0; mt < 4; mt++) {
                const int row = wm * 64 + mt * 16 + (lane & 15);
                const int c16 = ks * 2 + (lane >> 4);
                ldmx4(af[mt], abase + row * 128 + ((c16 ^ (row & 7)) * 16));
            }
#pragma unroll
            for (int nt = 0; nt < 4; nt++) {
                const int row = wn * 32 + nt * 8 + (lane & 7);
                const int c16 = ks * 2 + ((lane >> 3) & 1);
                ldmx2(bf[nt], bbase + row * 128 + ((c16 ^ (row & 7)) * 16));
            }
#pragma unroll
            for (int mt = 0; mt < 4; mt++)
#pragma unroll
                for (int nt = 0; nt < 4; nt++)
                    mma16816(acc[mt][nt], af[mt], bf[nt]);
        }
    }

    float* fC = reinterpret_cast<float*>(Cout);
    __nv_bfloat16* bC = reinterpret_cast<__nv_bfloat16*>(Cout);
#pragma unroll
    for (int mt = 0; mt < 4; mt++) {
        const int row0 = bm + wm * 64 + mt * 16 + (lane >> 2);
#pragma unroll
        for (int nt = 0; nt < 4; nt++) {
            const int col = bn + wn * 32 + nt * 8 + (lane & 3) * 2;
            const float b0 = bias[col], b1 = bias[col + 1];
            const float x0 = acc[mt][nt][0] + b0;
            const float x1 = acc[mt][nt][1] + b1;
            const float x2 = acc[mt][nt][2] + b0;
            const float x3 = acc[mt][nt][3] + b1;
            if (OUT_BF16) {
                *reinterpret_cast<uint32_t*>(bC + (size_t)row0 * DIM + col)       = pack_bf16(x0, x1);
                *reinterpret_cast<uint32_t*>(bC + (size_t)(row0 + 8) * DIM + col) = pack_bf16(x2, x3);
            } else {
                *reinterpret_cast<float2*>(fC + (size_t)row0 * DIM + col)       = make_float2(x0, x1);
                *reinterpret_cast<float2*>(fC + (size_t)(row0 + 8) * DIM + col) = make_float2(x2, x3);
            }
        }
    }
}

// ---------------- banded attention (round-2 verified) ----------------
__global__ __launch_bounds__(128)
void attn_kernel(const __nv_bfloat16* __restrict__ Q,
                 const __nv_bfloat16* __restrict__ K,
                 const __nv_bfloat16* __restrict__ V,
                 __nv_bfloat16* __restrict__ Out) {
    extern __shared__ char smem[];
    char* Ks = smem;             // 192 rows * 128B
    char* Vs = smem + 24576;     // 192 rows * 128B
    const int b = blockIdx.x >> 4, h = blockIdx.x & 15;
    const int qt = blockIdx.y;
    const int tid = threadIdx.x, lane = tid & 31, wid = tid >> 5;
    const int k0 = qt * 64 - 64;
    const size_t base = ((size_t)b * SEQ) * DIM + h * HDIM;

    for (int c = tid; c < 192 * 8; c += 128) {
        const int row = c >> 3, ch = c & 7;
        const int j = k0 + row;
        uint4 kv = make_uint4(0u, 0u, 0u, 0u), vv = make_uint4(0u, 0u, 0u, 0u);
        if (j >= 0 && j < SEQ) {
            kv = reinterpret_cast<const uint4*>(K + base + (size_t)j * DIM)[ch];
            vv = reinterpret_cast<const uint4*>(V + base + (size_t)j * DIM)[ch];
        }
        const int sw = ch ^ (row & 7);
        *reinterpret_cast<uint4*>(Ks + row * 128 + sw * 16) = kv;
        *reinterpret_cast<uint4*>(Vs + row * 128 + sw * 16) = vv;
    }
    __syncthreads();

    uint32_t qf[4][4];
    const int qr = qt * 64 + wid * 16 + (lane >> 2);
    {
        const __nv_bfloat16* q0 = Q + base + (size_t)qr * DIM;
        const __nv_bfloat16* q8 = Q + base + (size_t)(qr + 8) * DIM;
#pragma unroll
        for (int kt = 0; kt < 4; kt++) {
            const int c0 = kt * 16 + (lane & 3) * 2;
            qf[kt][0] = *reinterpret_cast<const uint32_t*>(q0 + c0);
            qf[kt][1] = *reinterpret_cast<const uint32_t*>(q8 + c0);
            qf[kt][2] = *reinterpret_cast<const uint32_t*>(q0 + c0 + 8);
            qf[kt][3] = *reinterpret_cast<const uint32_t*>(q8 + c0 + 8);
        }
    }

    float sc[24][4];
#pragma unroll
    for (int nt = 0; nt < 24; nt++)
#pragma unroll
        for (int i = 0; i < 4; i++) sc[nt][i] = 0.f;
#pragma unroll
    for (int kt = 0; kt < 4; kt++) {
#pragma unroll
        for (int nt = 0; nt < 24; nt++) {
            uint32_t kb[2];
            const int krow = nt * 8 + (lane & 7);
            const int ch = kt * 2 + ((lane >> 3) & 1);
            ldmx2(kb, (uint32_t)__cvta_generic_to_shared(Ks + krow * 128 + (ch ^ (krow & 7)) * 16));
            mma16816(sc[nt], qf[kt], kb);
        }
    }

    float mx0 = -1e30f, mx1 = -1e30f;
#pragma unroll
    for (int nt = 0; nt < 24; nt++) {
#pragma unroll
        for (int c = 0; c < 2; c++) {
            const int kj = k0 + nt * 8 + (lane & 3) * 2 + c;
            const bool inr = (kj >= 0) && (kj < SEQ);
            int d0 = qr - kj;     if (d0 < 0) d0 = -d0;
            int d1 = qr + 8 - kj; if (d1 < 0) d1 = -d1;
            const float s0 = (inr && d0 <= HALFWIN) ? sc[nt][c] * ATT_SCALE : -1e30f;
            const float s1 = (inr && d1 <= HALFWIN) ? sc[nt][c + 2] * ATT_SCALE : -1e30f;
            sc[nt][c] = s0; sc[nt][c + 2] = s1;
            mx0 = fmaxf(mx0, s0); mx1 = fmaxf(mx1, s1);
        }
    }
    mx0 = fmaxf(mx0, __shfl_xor_sync(0xffffffffu, mx0, 1));
    mx0 = fmaxf(mx0, __shfl_xor_sync(0xffffffffu, mx0, 2));
    mx1 = fmaxf(mx1, __shfl_xor_sync(0xffffffffu, mx1, 1));
    mx1 = fmaxf(mx1, __shfl_xor_sync(0xffffffffu, mx1, 2));
    float l0 = 0.f, l1 = 0.f;
#pragma unroll
    for (int nt = 0; nt < 24; nt++) {
#pragma unroll
        for (int c = 0; c < 2; c++) {
            const float p0 = __expf(sc[nt][c] - mx0);
            const float p1 = __expf(sc[nt][c + 2] - mx1);
            sc[nt][c] = p0; sc[nt][c + 2] = p1;
            l0 += p0; l1 += p1;
        }
    }
    l0 += __shfl_xor_sync(0xffffffffu, l0, 1);
    l0 += __shfl_xor_sync(0xffffffffu, l0, 2);
    l1 += __shfl_xor_sync(0xffffffffu, l1, 1);
    l1 += __shfl_xor_sync(0xffffffffu, l1, 2);

    float oacc[8][4];
#pragma unroll
    for (int dt = 0; dt < 8; dt++)
#pragma unroll
        for (int i = 0; i < 4; i++) oacc[dt][i] = 0.f;
#pragma unroll
    for (int jt = 0; jt < 12; jt++) {
        uint32_t pa[4];
        pa[0] = pack_bf16(sc[2 * jt][0], sc[2 * jt][1]);
        pa[1] = pack_bf16(sc[2 * jt][2], sc[2 * jt][3]);
        pa[2] = pack_bf16(sc[2 * jt + 1][0], sc[2 * jt + 1][1]);
        pa[3] = pack_bf16(sc[2 * jt + 1][2], sc[2 * jt + 1][3]);
        const int vrow = jt * 16 + (lane & 15);
#pragma unroll
        for (int dt = 0; dt < 8; dt++) {
            uint32_t vb[2];
            ldmx2t(vb, (uint32_t)__cvta_generic_to_shared(Vs + vrow * 128 + (dt ^ (vrow & 7)) * 16));
            mma16816(oacc[dt], pa, vb);
        }
    }

    const float i0 = 1.f / l0, i1 = 1.f / l1;
    __nv_bfloat16* ob = Out + base;
#pragma unroll
    for (int dt = 0; dt < 8; dt++) {
        const int col = dt * 8 + (lane & 3) * 2;
        *reinterpret_cast<uint32_t*>(ob + (size_t)qr * DIM + col) =
            pack_bf16(oacc[dt][0] * i0, oacc[dt][1] * i0);
        *reinterpret_cast<uint32_t*>(ob + (size_t)(qr + 8) * DIM + col) =
            pack_bf16(oacc[dt][2] * i1, oacc[dt][3] * i1);
    }
}

// ---------------- fused gate * attn, blend, LayerNorm ----------------
__global__ __launch_bounds__(256)
void final_kernel(const float* __restrict__ hid, const float* __restrict__ gate,
                  const float* __restrict__ yo, const float* __restrict__ gamma,
                  const float* __restrict__ beta, float* __restrict__ out) {
    const int row = blockIdx.x;
    const int tid = threadIdx.x;
    const size_t off = (size_t)row * DIM + tid * 4;
    const float4 hv = *reinterpret_cast<const float4*>(hid + off);
    const float4 gv = *reinterpret_cast<const float4*>(gate + off);
    const float4 yv = *reinterpret_cast<const float4*>(yo + off);
    float y[4];
    y[0] = 0.5f * hv.x + 0.5f * yv.x / (1.f + __expf(-gv.x));
    y[1] = 0.5f * hv.y + 0.5f * yv.y / (1.f + __expf(-gv.y));
    y[2] = 0.5f * hv.z + 0.5f * yv.z / (1.f + __expf(-gv.z));
    y[3] = 0.5f * hv.w + 0.5f * yv.w / (1.f + __expf(-gv.w));
    float s = y[0] + y[1] + y[2] + y[3];
    float s2 = y[0] * y[0] + y[1] * y[1] + y[2] * y[2] + y[3] * y[3];
#pragma unroll
    for (int o = 16; o > 0; o >>= 1) {
        s  += __shfl_xor_sync(0xffffffffu, s, o);
        s2 += __shfl_xor_sync(0xffffffffu, s2, o);
    }
    __shared__ float rs[8], rs2[8];
    if ((tid & 31) == 0) { rs[tid >> 5] = s; rs2[tid >> 5] = s2; }
    __syncthreads();
    float ts = 0.f, ts2 = 0.f;
#pragma unroll
    for (int w = 0; w < 8; w++) { ts += rs[w]; ts2 += rs2[w]; }
    const float mean = ts * (1.f / DIM);
    const float var = ts2 * (1.f / DIM) - mean * mean;
    const float rstd = rsqrtf(var + 1e-5f);
    const float4 gm = *reinterpret_cast<const float4*>(gamma + tid * 4);
    const float4 bt = *reinterpret_cast<const float4*>(beta + tid * 4);
    float4 o4;
    o4.x = (y[0] - mean) * rstd * gm.x + bt.x;
    o4.y = (y[1] - mean) * rstd * gm.y + bt.y;
    o4.z = (y[2] - mean) * rstd * gm.z + bt.z;
    o4.w = (y[3] - mean) * rstd * gm.w + bt.w;
    *reinterpret_cast<float4*>(out + off) = o4;
}

// ---------------- launch ----------------
extern "C" void kernel_launch(void* const* d_in, const int* in_sizes, int n_in,
                              void* d_out, int out_size) {
    (void)in_sizes; (void)n_in; (void)out_size;
    const float* hidden = (const float*)d_in[0];
    const float* cross  = (const float*)d_in[1];
    const float* Wq = (const float*)d_in[2];  const float* bq = (const float*)d_in[3];
    const float* Wk = (const float*)d_in[4];  const float* bk = (const float*)d_in[5];
    const float* Wv = (const float*)d_in[6];  const float* bv = (const float*)d_in[7];
    const float* Wo = (const float*)d_in[8];  const float* bo = (const float*)d_in[9];
    const float* Wg = (const float*)d_in[10]; const float* bg = (const float*)d_in[11];
    const float* gamma = (const float*)d_in[12];
    const float* beta  = (const float*)d_in[13];

    __nv_bfloat16 *hb, *cb, *w5, *q, *k, *v, *at;
    float *gate, *yo;
    cudaGetSymbolAddress((void**)&hb, g_hb);
    cudaGetSymbolAddress((void**)&cb, g_cb);
    cudaGetSymbolAddress((void**)&w5, g_w5);
    cudaGetSymbolAddress((void**)&q,  g_q);
    cudaGetSymbolAddress((void**)&k,  g_k);
    cudaGetSymbolAddress((void**)&v,  g_v);
    cudaGetSymbolAddress((void**)&at, g_attn);
    cudaGetSymbolAddress((void**)&gate, g_gate);
    cudaGetSymbolAddress((void**)&yo,   g_yo);

    cudaFuncSetAttribute(gemm_kernel<true>,
                         cudaFuncAttributeMaxDynamicSharedMemorySize, GEMM_SMEM);
    cudaFuncSetAttribute(gemm_kernel<false>,
                         cudaFuncAttributeMaxDynamicSharedMemorySize, GEMM_SMEM);

    const int nXDvec = MROWS * DIM / 4;
    cvt2_kernel<<<1024, 256>>>(hidden, hb, cross, cb, nXDvec);
    cvtw_kernel<<<dim3(128, 5), 256>>>(Wq, Wk, Wv, Wo, Wg);

    const __nv_bfloat16* wq = w5;
    const __nv_bfloat16* wk = w5 + 1 * (size_t)DIM * DIM;
    const __nv_bfloat16* wv = w5 + 2 * (size_t)DIM * DIM;
    const __nv_bfloat16* wo = w5 + 3 * (size_t)DIM * DIM;
    const __nv_bfloat16* wg = w5 + 4 * (size_t)DIM * DIM;

    dim3 gg(DIM / BN, MROWS / BM);  // (8, 64)
    gemm_kernel<true ><<<gg, 256, GEMM_SMEM>>>(hb, wq, bq, q);
    gemm_kernel<true ><<<gg, 256, GEMM_SMEM>>>(cb, wk, bk, k);
    gemm_kernel<true ><<<gg, 256, GEMM_SMEM>>>(cb, wv, bv, v);
    gemm_kernel<false><<<gg, 256, GEMM_SMEM>>>(hb, wg, bg, gate);

    attn_kernel<<<dim3(BATCH * NH, SEQ / 64), 128, 49152>>>(q, k, v, at);

    gemm_kernel<false><<<gg, 256, GEMM_SMEM>>>(at, wo, bo, yo);

    final_kernel<<<MROWS, 256>>>(hidden, gate, yo, gamma, beta, (float*)d_out);
}

// round 8
// speedup vs baseline: 1.2870x; 1.0120x over previous
#include <cuda_runtime.h>
#include <cuda_bf16.h>
#include <cstdint>
#include <cstddef>

#define DEVI __device__ __forceinline__

namespace {
constexpr int BATCH = 16, SEQ = 512, DIM = 1024, NH = 16, HDIM = 64;
constexpr int MROWS = BATCH * SEQ;      // 8192
constexpr int HALFWIN = 64;
constexpr float ATT_SCALE = 0.125f;     // 1/sqrt(64)
constexpr int BM = 128, BN = 128, BK = 64;   // K-chunk = 64 bf16 = 128B row (XOR swizzle)
constexpr int KT = DIM / BK;                 // 16
constexpr int NST = 3;
constexpr int STAGE_BYTES = (BM + BN) * 128; // 32768 (A 16KB + B 16KB)
constexpr int GEMM_SMEM = NST * STAGE_BYTES + 256;
}

// ---------------- scratch (device globals; no allocation allowed) ----------------
__device__ __nv_bfloat16 g_hb[MROWS * DIM];
__device__ __nv_bfloat16 g_cb[MROWS * DIM];
__device__ __nv_bfloat16 g_w5[5 * DIM * DIM];   // Wq,Wk,Wv,Wo,Wg packed
__device__ __nv_bfloat16 g_q[MROWS * DIM];
__device__ __nv_bfloat16 g_k[MROWS * DIM];
__device__ __nv_bfloat16 g_v[MROWS * DIM];
__device__ __nv_bfloat16 g_attn[MROWS * DIM];
__device__ __nv_bfloat16 g_gate[MROWS * DIM];   // bf16 now
__device__ __nv_bfloat16 g_yo[MROWS * DIM];     // bf16 now

// ---------------- small helpers ----------------
DEVI uint32_t pack_bf16(float a, float b) {
    __nv_bfloat162 t;
    t.x = __float2bfloat16(a);
    t.y = __float2bfloat16(b);
    return *reinterpret_cast<uint32_t*>(&t);
}
DEVI void mma16816(float* c, const uint32_t* a, const uint32_t* b) {
    asm volatile(
        "mma.sync.aligned.m16n8k16.row.col.f32.bf16.bf16.f32 "
        "{%0,%1,%2,%3}, {%4,%5,%6,%7}, {%8,%9}, {%0,%1,%2,%3};"
        : "+f"(c[0]), "+f"(c[1]), "+f"(c[2]), "+f"(c[3])
        : "r"(a[0]), "r"(a[1]), "r"(a[2]), "r"(a[3]), "r"(b[0]), "r"(b[1]));
}
DEVI void ldmx4(uint32_t* r, uint32_t addr) {
    asm volatile("ldmatrix.sync.aligned.m8n8.x4.shared.b16 {%0,%1,%2,%3}, [%4];"
                 : "=r"(r[0]), "=r"(r[1]), "=r"(r[2]), "=r"(r[3]) : "r"(addr));
}
DEVI void ldmx2(uint32_t* r, uint32_t addr) {
    asm volatile("ldmatrix.sync.aligned.m8n8.x2.shared.b16 {%0,%1}, [%2];"
                 : "=r"(r[0]), "=r"(r[1]) : "r"(addr));
}
DEVI void ldmx2t(uint32_t* r, uint32_t addr) {
    asm volatile("ldmatrix.sync.aligned.m8n8.x2.trans.shared.b16 {%0,%1}, [%2];"
                 : "=r"(r[0]), "=r"(r[1]) : "r"(addr));
}
DEVI void cpasync16(uint32_t dst, const void* src) {
    asm volatile("cp.async.cg.shared.global [%0], [%1], 16;" :: "r"(dst), "l"(src));
}

// ---------------- fp32 -> bf16 conversions ----------------
__global__ void cvt2_kernel(const float* __restrict__ s0, __nv_bfloat16* __restrict__ d0,
                            const float* __restrict__ s1, __nv_bfloat16* __restrict__ d1,
                            int nvec) {
    const int stride = gridDim.x * blockDim.x;
    for (int i = blockIdx.x * blockDim.x + threadIdx.x; i < 2 * nvec; i += stride) {
        const bool second = (i >= nvec);
        const float* src = second ? s1 : s0;
        __nv_bfloat16* dst = second ? d1 : d0;
        const int idx = (second ? i - nvec : i) * 4;
        float4 f = *reinterpret_cast<const float4*>(src + idx);
        __nv_bfloat162 lo, hi;
        lo.x = __float2bfloat16(f.x); lo.y = __float2bfloat16(f.y);
        hi.x = __float2bfloat16(f.z); hi.y = __float2bfloat16(f.w);
        *reinterpret_cast<__nv_bfloat162*>(dst + idx)     = lo;
        *reinterpret_cast<__nv_bfloat162*>(dst + idx + 2) = hi;
    }
}
__global__ void cvtw_kernel(const float* __restrict__ wq, const float* __restrict__ wk,
                            const float* __restrict__ wv, const float* __restrict__ wo,
                            const float* __restrict__ wg) {
    const int which = blockIdx.y;
    const float* src = (which == 0) ? wq : (which == 1) ? wk : (which == 2) ? wv
                     : (which == 3) ? wo : wg;
    __nv_bfloat16* dst = g_w5 + (size_t)which * DIM * DIM;
    const int nvec = DIM * DIM / 4;
    const int stride = gridDim.x * blockDim.x;
    for (int i = blockIdx.x * blockDim.x + threadIdx.x; i < nvec; i += stride) {
        const int idx = i * 4;
        float4 f = *reinterpret_cast<const float4*>(src + idx);
        __nv_bfloat162 lo, hi;
        lo.x = __float2bfloat16(f.x); lo.y = __float2bfloat16(f.y);
        hi.x = __float2bfloat16(f.z); hi.y = __float2bfloat16(f.w);
        *reinterpret_cast<__nv_bfloat162*>(dst + idx)     = lo;
        *reinterpret_cast<__nv_bfloat162*>(dst + idx + 2) = hi;
    }
}

// ---------------- bf16 GEMM: C[M,N] = A[M,K] @ W[N,K]^T + bias, bf16 out ----------
// 128x128x64 tiles, 3-stage cp.async pipeline + register fragment double-buffering.
__global__ __launch_bounds__(256, 2)
void gemm_kernel(const __nv_bfloat16* __restrict__ A,
                 const __nv_bfloat16* __restrict__ W,
                 const float* __restrict__ bias,
                 __nv_bfloat16* __restrict__ Cout) {
    extern __shared__ char dsm[];
    const uint32_t sb = ((uint32_t)__cvta_generic_to_shared(dsm) + 127) & ~127u;
    const int tid  = threadIdx.x;
    const int lane = tid & 31, wid = tid >> 5;
    const int wm = wid >> 2, wn = wid & 3;
    const int bm = blockIdx.y * BM, bn = blockIdx.x * BN;

    float acc[4][4][4];
#pragma unroll
    for (int mt = 0; mt < 4; mt++)
#pragma unroll
        for (int nt = 0; nt < 4; nt++)
#pragma unroll
            for (int i = 0; i < 4; i++) acc[mt][nt][i] = 0.f;

    auto stage = [&](int kt) {
        const uint32_t abase = sb + (kt % NST) * STAGE_BYTES;
        const uint32_t bbase = abase + BM * 128;
#pragma unroll
        for (int s = 0; s < 4; s++) {
            const int i = tid + s * 256;
            const int r = i >> 3, c = i & 7;
            cpasync16(abase + r * 128 + ((c ^ (r & 7)) * 16),
                      A + (size_t)(bm + r) * DIM + kt * BK + c * 8);
        }
#pragma unroll
        for (int s = 0; s < 4; s++) {
            const int i = tid + s * 256;
            const int r = i >> 3, c = i & 7;
            cpasync16(bbase + r * 128 + ((c ^ (r & 7)) * 16),
                      W + (size_t)(bn + r) * DIM + kt * BK + c * 8);
        }
        asm volatile("cp.async.commit_group;" ::: "memory");
    };

    uint32_t af[2][4][4], bf[2][4][2];
    auto load_frags = [&](uint32_t abase, uint32_t bbase, int ks, int p) {
#pragma unroll
        for (int mt = 0; mt < 4; mt++) {
            const int row = wm * 64 + mt * 16 + (lane & 15);
            const int c16 = ks * 2 + (lane >> 4);
            ldmx4(af[p][mt], abase + row * 128 + ((c16 ^ (row & 7)) * 16));
        }
#pragma unroll
        for (int j = 0; j < 2; j++) {
            // x4 covering nt = 2j and 2j+1: lanes 0-15 -> nt=2j rows/k-halves, 16-31 -> nt=2j+1
            const int row = wn * 32 + j * 16 + ((lane >> 4) & 1) * 8 + (lane & 7);
            const int c16 = ks * 2 + ((lane >> 3) & 1);
            uint32_t r[4];
            ldmx4(r, bbase + row * 128 + ((c16 ^ (row & 7)) * 16));
            bf[p][2 * j][0]     = r[0]; bf[p][2 * j][1]     = r[1];
            bf[p][2 * j + 1][0] = r[2]; bf[p][2 * j + 1][1] = r[3];
        }
    };

    stage(0);
    stage(1);
    for (int kt = 0; kt < KT; kt++) {
        if (kt < KT - 1) asm volatile("cp.async.wait_group 1;" ::: "memory");
        else             asm volatile("cp.async.wait_group 0;" ::: "memory");
        __syncthreads();
        if (kt + 2 < KT) stage(kt + 2);
        const uint32_t abase = sb + (kt % NST) * STAGE_BYTES;
        const uint32_t bbase = abase + BM * 128;
        load_frags(abase, bbase, 0, 0);
#pragma unroll
        for (int ks = 0; ks < BK / 16; ks++) {
            const int cur = ks & 1;
            if (ks < BK / 16 - 1) load_frags(abase, bbase, ks + 1, cur ^ 1);
#pragma unroll
            for (int mt = 0; mt < 4; mt++)
#pragma unroll
                for (int nt = 0; nt < 4; nt++)
                    mma16816(acc[mt][nt], af[cur][mt], bf[cur][nt]);
        }
    }

#pragma unroll
    for (int mt = 0; mt < 4; mt++) {
        const int row0 = bm + wm * 64 + mt * 16 + (lane >> 2);
#pragma unroll
        for (int nt = 0; nt < 4; nt++) {
            const int col = bn + wn * 32 + nt * 8 + (lane & 3) * 2;
            const float b0 = bias[col], b1 = bias[col + 1];
            *reinterpret_cast<uint32_t*>(Cout + (size_t)row0 * DIM + col) =
                pack_bf16(acc[mt][nt][0] + b0, acc[mt][nt][1] + b1);
            *reinterpret_cast<uint32_t*>(Cout + (size_t)(row0 + 8) * DIM + col) =
                pack_bf16(acc[mt][nt][2] + b0, acc[mt][nt][3] + b1);
        }
    }
}

// ---------------- banded attention (round-2 verified) ----------------
__global__ __launch_bounds__(128)
void attn_kernel(const __nv_bfloat16* __restrict__ Q,
                 const __nv_bfloat16* __restrict__ K,
                 const __nv_bfloat16* __restrict__ V,
                 __nv_bfloat16* __restrict__ Out) {
    extern __shared__ char smem[];
    char* Ks = smem;             // 192 rows * 128B
    char* Vs = smem + 24576;     // 192 rows * 128B
    const int b = blockIdx.x >> 4, h = blockIdx.x & 15;
    const int qt = blockIdx.y;
    const int tid = threadIdx.x, lane = tid & 31, wid = tid >> 5;
    const int k0 = qt * 64 - 64;
    const size_t base = ((size_t)b * SEQ) * DIM + h * HDIM;

    for (int c = tid; c < 192 * 8; c += 128) {
        const int row = c >> 3, ch = c & 7;
        const int j = k0 + row;
        uint4 kv = make_uint4(0u, 0u, 0u, 0u), vv = make_uint4(0u, 0u, 0u, 0u);
        if (j >= 0 && j < SEQ) {
            kv = reinterpret_cast<const uint4*>(K + base + (size_t)j * DIM)[ch];
            vv = reinterpret_cast<const uint4*>(V + base + (size_t)j * DIM)[ch];
        }
        const int sw = ch ^ (row & 7);
        *reinterpret_cast<uint4*>(Ks + row * 128 + sw * 16) = kv;
        *reinterpret_cast<uint4*>(Vs + row * 128 + sw * 16) = vv;
    }
    __syncthreads();

    uint32_t qf[4][4];
    const int qr = qt * 64 + wid * 16 + (lane >> 2);
    {
        const __nv_bfloat16* q0 = Q + base + (size_t)qr * DIM;
        const __nv_bfloat16* q8 = Q + base + (size_t)(qr + 8) * DIM;
#pragma unroll
        for (int kt = 0; kt < 4; kt++) {
            const int c0 = kt * 16 + (lane & 3) * 2;
            qf[kt][0] = *reinterpret_cast<const uint32_t*>(q0 + c0);
            qf[kt][1] = *reinterpret_cast<const uint32_t*>(q8 + c0);
            qf[kt][2] = *reinterpret_cast<const uint32_t*>(q0 + c0 + 8);
            qf[kt][3] = *reinterpret_cast<const uint32_t*>(q8 + c0 + 8);
        }
    }

    float sc[24][4];
#pragma unroll
    for (int nt = 0; nt < 24; nt++)
#pragma unroll
        for (int i = 0; i < 4; i++) sc[nt][i] = 0.f;
#pragma unroll
    for (int kt = 0; kt < 4; kt++) {
#pragma unroll
        for (int nt = 0; nt < 24; nt++) {
            uint32_t kb[2];
            const int krow = nt * 8 + (lane & 7);
            const int ch = kt * 2 + ((lane >> 3) & 1);
            ldmx2(kb, (uint32_t)__cvta_generic_to_shared(Ks + krow * 128 + (ch ^ (krow & 7)) * 16));
            mma16816(sc[nt], qf[kt], kb);
        }
    }

    float mx0 = -1e30f, mx1 = -1e30f;
#pragma unroll
    for (int nt = 0; nt < 24; nt++) {
#pragma unroll
        for (int c = 0; c < 2; c++) {
            const int kj = k0 + nt * 8 + (lane & 3) * 2 + c;
            const bool inr = (kj >= 0) && (kj < SEQ);
            int d0 = qr - kj;     if (d0 < 0) d0 = -d0;
            int d1 = qr + 8 - kj; if (d1 < 0) d1 = -d1;
            const float s0 = (inr && d0 <= HALFWIN) ? sc[nt][c] * ATT_SCALE : -1e30f;
            const float s1 = (inr && d1 <= HALFWIN) ? sc[nt][c + 2] * ATT_SCALE : -1e30f;
            sc[nt][c] = s0; sc[nt][c + 2] = s1;
            mx0 = fmaxf(mx0, s0); mx1 = fmaxf(mx1, s1);
        }
    }
    mx0 = fmaxf(mx0, __shfl_xor_sync(0xffffffffu, mx0, 1));
    mx0 = fmaxf(mx0, __shfl_xor_sync(0xffffffffu, mx0, 2));
    mx1 = fmaxf(mx1, __shfl_xor_sync(0xffffffffu, mx1, 1));
    mx1 = fmaxf(mx1, __shfl_xor_sync(0xffffffffu, mx1, 2));
    float l0 = 0.f, l1 = 0.f;
#pragma unroll
    for (int nt = 0; nt < 24; nt++) {
#pragma unroll
        for (int c = 0; c < 2; c++) {
            const float p0 = __expf(sc[nt][c] - mx0);
            const float p1 = __expf(sc[nt][c + 2] - mx1);
            sc[nt][c] = p0; sc[nt][c + 2] = p1;
            l0 += p0; l1 += p1;
        }
    }
    l0 += __shfl_xor_sync(0xffffffffu, l0, 1);
    l0 += __shfl_xor_sync(0xffffffffu, l0, 2);
    l1 += __shfl_xor_sync(0xffffffffu, l1, 1);
    l1 += __shfl_xor_sync(0xffffffffu, l1, 2);

    float oacc[8][4];
#pragma unroll
    for (int dt = 0; dt < 8; dt++)
#pragma unroll
        for (int i = 0; i < 4; i++) oacc[dt][i] = 0.f;
#pragma unroll
    for (int jt = 0; jt < 12; jt++) {
        uint32_t pa[4];
        pa[0] = pack_bf16(sc[2 * jt][0], sc[2 * jt][1]);
        pa[1] = pack_bf16(sc[2 * jt][2], sc[2 * jt][3]);
        pa[2] = pack_bf16(sc[2 * jt + 1][0], sc[2 * jt + 1][1]);
        pa[3] = pack_bf16(sc[2 * jt + 1][2], sc[2 * jt + 1][3]);
        const int vrow = jt * 16 + (lane & 15);
#pragma unroll
        for (int dt = 0; dt < 8; dt++) {
            uint32_t vb[2];
            ldmx2t(vb, (uint32_t)__cvta_generic_to_shared(Vs + vrow * 128 + (dt ^ (vrow & 7)) * 16));
            mma16816(oacc[dt], pa, vb);
        }
    }

    const float i0 = 1.f / l0, i1 = 1.f / l1;
    __nv_bfloat16* ob = Out + base;
#pragma unroll
    for (int dt = 0; dt < 8; dt++) {
        const int col = dt * 8 + (lane & 3) * 2;
        *reinterpret_cast<uint32_t*>(ob + (size_t)qr * DIM + col) =
            pack_bf16(oacc[dt][0] * i0, oacc[dt][1] * i0);
        *reinterpret_cast<uint32_t*>(ob + (size_t)(qr + 8) * DIM + col) =
            pack_bf16(oacc[dt][2] * i1, oacc[dt][3] * i1);
    }
}

// ---------------- fused gate * attn, blend, LayerNorm (bf16 gate/yo) --------------
__global__ __launch_bounds__(256)
void final_kernel(const float* __restrict__ hid, const __nv_bfloat16* __restrict__ gate,
                  const __nv_bfloat16* __restrict__ yo, const float* __restrict__ gamma,
                  const float* __restrict__ beta, float* __restrict__ out) {
    const int row = blockIdx.x;
    const int tid = threadIdx.x;
    const size_t off = (size_t)row * DIM + tid * 4;
    const float4 hv = *reinterpret_cast<const float4*>(hid + off);
    const uint2 g2 = *reinterpret_cast<const uint2*>(gate + off);
    const uint2 y2 = *reinterpret_cast<const uint2*>(yo + off);
    const __nv_bfloat162 ga = *reinterpret_cast<const __nv_bfloat162*>(&g2.x);
    const __nv_bfloat162 gb = *reinterpret_cast<const __nv_bfloat162*>(&g2.y);
    const __nv_bfloat162 ya = *reinterpret_cast<const __nv_bfloat162*>(&y2.x);
    const __nv_bfloat162 yb = *reinterpret_cast<const __nv_bfloat162*>(&y2.y);
    const float gv[4] = {__bfloat162float(ga.x), __bfloat162float(ga.y),
                         __bfloat162float(gb.x), __bfloat162float(gb.y)};
    const float yv[4] = {__bfloat162float(ya.x), __bfloat162float(ya.y),
                         __bfloat162float(yb.x), __bfloat162float(yb.y)};
    const float hvv[4] = {hv.x, hv.y, hv.z, hv.w};
    float y[4];
#pragma unroll
    for (int i = 0; i < 4; i++)
        y[i] = 0.5f * hvv[i] + 0.5f * yv[i] / (1.f + __expf(-gv[i]));
    float s = y[0] + y[1] + y[2] + y[3];
    float s2 = y[0] * y[0] + y[1] * y[1] + y[2] * y[2] + y[3] * y[3];
#pragma unroll
    for (int o = 16; o > 0; o >>= 1) {
        s  += __shfl_xor_sync(0xffffffffu, s, o);
        s2 += __shfl_xor_sync(0xffffffffu, s2, o);
    }
    __shared__ float rs[8], rs2[8];
    if ((tid & 31) == 0) { rs[tid >> 5] = s; rs2[tid >> 5] = s2; }
    __syncthreads();
    float ts = 0.f, ts2 = 0.f;
#pragma unroll
    for (int w = 0; w < 8; w++) { ts += rs[w]; ts2 += rs2[w]; }
    const float mean = ts * (1.f / DIM);
    const float var = ts2 * (1.f / DIM) - mean * mean;
    const float rstd = rsqrtf(var + 1e-5f);
    const float4 gm = *reinterpret_cast<const float4*>(gamma + tid * 4);
    const float4 bt = *reinterpret_cast<const float4*>(beta + tid * 4);
    float4 o4;
    o4.x = (y[0] - mean) * rstd * gm.x + bt.x;
    o4.y = (y[1] - mean) * rstd * gm.y + bt.y;
    o4.z = (y[2] - mean) * rstd * gm.z + bt.z;
    o4.w = (y[3] - mean) * rstd * gm.w + bt.w;
    *reinterpret_cast<float4*>(out + off) = o4;
}

// ---------------- launch ----------------
extern "C" void kernel_launch(void* const* d_in, const int* in_sizes, int n_in,
                              void* d_out, int out_size) {
    (void)in_sizes; (void)n_in; (void)out_size;
    const float* hidden = (const float*)d_in[0];
    const float* cross  = (const float*)d_in[1];
    const float* Wq = (const float*)d_in[2];  const float* bq = (const float*)d_in[3];
    const float* Wk = (const float*)d_in[4];  const float* bk = (const float*)d_in[5];
    const float* Wv = (const float*)d_in[6];  const float* bv = (const float*)d_in[7];
    const float* Wo = (const float*)d_in[8];  const float* bo = (const float*)d_in[9];
    const float* Wg = (const float*)d_in[10]; const float* bg = (const float*)d_in[11];
    const float* gamma = (const float*)d_in[12];
    const float* beta  = (const float*)d_in[13];

    __nv_bfloat16 *hb, *cb, *w5, *q, *k, *v, *at, *gate, *yo;
    cudaGetSymbolAddress((void**)&hb, g_hb);
    cudaGetSymbolAddress((void**)&cb, g_cb);
    cudaGetSymbolAddress((void**)&w5, g_w5);
    cudaGetSymbolAddress((void**)&q,  g_q);
    cudaGetSymbolAddress((void**)&k,  g_k);
    cudaGetSymbolAddress((void**)&v,  g_v);
    cudaGetSymbolAddress((void**)&at, g_attn);
    cudaGetSymbolAddress((void**)&gate, g_gate);
    cudaGetSymbolAddress((void**)&yo,   g_yo);

    cudaFuncSetAttribute(gemm_kernel,
                         cudaFuncAttributeMaxDynamicSharedMemorySize, GEMM_SMEM);

    const int nXDvec = MROWS * DIM / 4;
    cvt2_kernel<<<1024, 256>>>(hidden, hb, cross, cb, nXDvec);
    cvtw_kernel<<<dim3(128, 5), 256>>>(Wq, Wk, Wv, Wo, Wg);

    const __nv_bfloat16* wq = w5;
    const __nv_bfloat16* wk = w5 + 1 * (size_t)DIM * DIM;
    const __nv_bfloat16* wv = w5 + 2 * (size_t)DIM * DIM;
    const __nv_bfloat16* wo = w5 + 3 * (size_t)DIM * DIM;
    const __nv_bfloat16* wg = w5 + 4 * (size_t)DIM * DIM;

    dim3 gg(DIM / BN, MROWS / BM);  // (8, 64)
    gemm_kernel<<<gg, 256, GEMM_SMEM>>>(hb, wq, bq, q);
    gemm_kernel<<<gg, 256, GEMM_SMEM>>>(cb, wk, bk, k);
    gemm_kernel<<<gg, 256, GEMM_SMEM>>>(cb, wv, bv, v);
    gemm_kernel<<<gg, 256, GEMM_SMEM>>>(hb, wg, bg, gate);

    attn_kernel<<<dim3(BATCH * NH, SEQ / 64), 128, 49152>>>(q, k, v, at);

    gemm_kernel<<<gg, 256, GEMM_SMEM>>>(at, wo, bo, yo);

    final_kernel<<<MROWS, 256>>>(hidden, gate, yo, gamma, beta, (float*)d_out);
}

// round 9
// speedup vs baseline: 1.4157x; 1.1001x over previous
#include <cuda_runtime.h>
#include <cuda_bf16.h>
#include <cstdint>
#include <cstddef>

#define DEVI __device__ __forceinline__

namespace {
constexpr int BATCH = 16, SEQ = 512, DIM = 1024, NH = 16, HDIM = 64;
constexpr int MROWS = BATCH * SEQ;      // 8192
constexpr int HALFWIN = 64;
constexpr float ATT_SCALE = 0.125f;     // 1/sqrt(64)
constexpr int BM = 128, BN = 128, BK = 64;   // K-chunk = 64 bf16 = 128B row (XOR swizzle)
constexpr int KT = DIM / BK;                 // 16
constexpr int NST = 3;
constexpr int STAGE_BYTES = (BM + BN) * 128; // 32768 (A 16KB + B 16KB)
constexpr int GEMM_SMEM = NST * STAGE_BYTES + 256;
}

// ---------------- scratch (device globals; no allocation allowed) ----------------
__device__ __nv_bfloat16 g_hb[MROWS * DIM];
__device__ __nv_bfloat16 g_cb[MROWS * DIM];
__device__ __nv_bfloat16 g_w5[5 * DIM * DIM];   // Wq,Wk,Wv,Wo,Wg packed
__device__ __nv_bfloat16 g_q[MROWS * DIM];
__device__ __nv_bfloat16 g_k[MROWS * DIM];
__device__ __nv_bfloat16 g_v[MROWS * DIM];
__device__ __nv_bfloat16 g_attn[MROWS * DIM];
__device__ __nv_bfloat16 g_gate[MROWS * DIM];
__device__ __nv_bfloat16 g_yo[MROWS * DIM];

// ---------------- small helpers ----------------
DEVI uint32_t pack_bf16(float a, float b) {
    __nv_bfloat162 t;
    t.x = __float2bfloat16(a);
    t.y = __float2bfloat16(b);
    return *reinterpret_cast<uint32_t*>(&t);
}
DEVI void mma16816(float* c, const uint32_t* a, const uint32_t* b) {
    asm volatile(
        "mma.sync.aligned.m16n8k16.row.col.f32.bf16.bf16.f32 "
        "{%0,%1,%2,%3}, {%4,%5,%6,%7}, {%8,%9}, {%0,%1,%2,%3};"
        : "+f"(c[0]), "+f"(c[1]), "+f"(c[2]), "+f"(c[3])
        : "r"(a[0]), "r"(a[1]), "r"(a[2]), "r"(a[3]), "r"(b[0]), "r"(b[1]));
}
DEVI void ldmx4(uint32_t* r, uint32_t addr) {
    asm volatile("ldmatrix.sync.aligned.m8n8.x4.shared.b16 {%0,%1,%2,%3}, [%4];"
                 : "=r"(r[0]), "=r"(r[1]), "=r"(r[2]), "=r"(r[3]) : "r"(addr));
}
DEVI void ldmx2(uint32_t* r, uint32_t addr) {
    asm volatile("ldmatrix.sync.aligned.m8n8.x2.shared.b16 {%0,%1}, [%2];"
                 : "=r"(r[0]), "=r"(r[1]) : "r"(addr));
}
DEVI void ldmx2t(uint32_t* r, uint32_t addr) {
    asm volatile("ldmatrix.sync.aligned.m8n8.x2.trans.shared.b16 {%0,%1}, [%2];"
                 : "=r"(r[0]), "=r"(r[1]) : "r"(addr));
}
DEVI void cpasync16(uint32_t dst, const void* src) {
    asm volatile("cp.async.cg.shared.global [%0], [%1], 16;" :: "r"(dst), "l"(src));
}

// ---------------- fp32 -> bf16 conversions ----------------
__global__ void cvt2_kernel(const float* __restrict__ s0, __nv_bfloat16* __restrict__ d0,
                            const float* __restrict__ s1, __nv_bfloat16* __restrict__ d1,
                            int nvec) {
    const int stride = gridDim.x * blockDim.x;
    for (int i = blockIdx.x * blockDim.x + threadIdx.x; i < 2 * nvec; i += stride) {
        const bool second = (i >= nvec);
        const float* src = second ? s1 : s0;
        __nv_bfloat16* dst = second ? d1 : d0;
        const int idx = (second ? i - nvec : i) * 4;
        float4 f = *reinterpret_cast<const float4*>(src + idx);
        __nv_bfloat162 lo, hi;
        lo.x = __float2bfloat16(f.x); lo.y = __float2bfloat16(f.y);
        hi.x = __float2bfloat16(f.z); hi.y = __float2bfloat16(f.w);
        *reinterpret_cast<__nv_bfloat162*>(dst + idx)     = lo;
        *reinterpret_cast<__nv_bfloat162*>(dst + idx + 2) = hi;
    }
}
__global__ void cvtw_kernel(const float* __restrict__ wq, const float* __restrict__ wk,
                            const float* __restrict__ wv, const float* __restrict__ wo,
                            const float* __restrict__ wg) {
    const int which = blockIdx.y;
    const float* src = (which == 0) ? wq : (which == 1) ? wk : (which == 2) ? wv
                     : (which == 3) ? wo : wg;
    __nv_bfloat16* dst = g_w5 + (size_t)which * DIM * DIM;
    const int nvec = DIM * DIM / 4;
    const int stride = gridDim.x * blockDim.x;
    for (int i = blockIdx.x * blockDim.x + threadIdx.x; i < nvec; i += stride) {
        const int idx = i * 4;
        float4 f = *reinterpret_cast<const float4*>(src + idx);
        __nv_bfloat162 lo, hi;
        lo.x = __float2bfloat16(f.x); lo.y = __float2bfloat16(f.y);
        hi.x = __float2bfloat16(f.z); hi.y = __float2bfloat16(f.w);
        *reinterpret_cast<__nv_bfloat162*>(dst + idx)     = lo;
        *reinterpret_cast<__nv_bfloat162*>(dst + idx + 2) = hi;
    }
}

// ---------------- bf16 GEMM body: C[M,N] = A[M,K] @ W[N,K]^T + bias, bf16 out -----
// 128x128x64 tiles, 3-stage cp.async pipeline + register fragment double-buffering.
DEVI void gemm_body(int bx, int by,
                    const __nv_bfloat16* __restrict__ A,
                    const __nv_bfloat16* __restrict__ W,
                    const float* __restrict__ bias,
                    __nv_bfloat16* __restrict__ Cout) {
    extern __shared__ char dsm[];
    const uint32_t sb = ((uint32_t)__cvta_generic_to_shared(dsm) + 127) & ~127u;
    const int tid  = threadIdx.x;
    const int lane = tid & 31, wid = tid >> 5;
    const int wm = wid >> 2, wn = wid & 3;
    const int bm = by * BM, bn = bx * BN;

    float acc[4][4][4];
#pragma unroll
    for (int mt = 0; mt < 4; mt++)
#pragma unroll
        for (int nt = 0; nt < 4; nt++)
#pragma unroll
            for (int i = 0; i < 4; i++) acc[mt][nt][i] = 0.f;

    auto stage = [&](int kt) {
        const uint32_t abase = sb + (kt % NST) * STAGE_BYTES;
        const uint32_t bbase = abase + BM * 128;
#pragma unroll
        for (int s = 0; s < 4; s++) {
            const int i = tid + s * 256;
            const int r = i >> 3, c = i & 7;
            cpasync16(abase + r * 128 + ((c ^ (r & 7)) * 16),
                      A + (size_t)(bm + r) * DIM + kt * BK + c * 8);
        }
#pragma unroll
        for (int s = 0; s < 4; s++) {
            const int i = tid + s * 256;
            const int r = i >> 3, c = i & 7;
            cpasync16(bbase + r * 128 + ((c ^ (r & 7)) * 16),
                      W + (size_t)(bn + r) * DIM + kt * BK + c * 8);
        }
        asm volatile("cp.async.commit_group;" ::: "memory");
    };

    uint32_t af[2][4][4], bf[2][4][2];
    auto load_frags = [&](uint32_t abase, uint32_t bbase, int ks, int p) {
#pragma unroll
        for (int mt = 0; mt < 4; mt++) {
            const int row = wm * 64 + mt * 16 + (lane & 15);
            const int c16 = ks * 2 + (lane >> 4);
            ldmx4(af[p][mt], abase + row * 128 + ((c16 ^ (row & 7)) * 16));
        }
#pragma unroll
        for (int j = 0; j < 2; j++) {
            const int row = wn * 32 + j * 16 + ((lane >> 4) & 1) * 8 + (lane & 7);
            const int c16 = ks * 2 + ((lane >> 3) & 1);
            uint32_t r[4];
            ldmx4(r, bbase + row * 128 + ((c16 ^ (row & 7)) * 16));
            bf[p][2 * j][0]     = r[0]; bf[p][2 * j][1]     = r[1];
            bf[p][2 * j + 1][0] = r[2]; bf[p][2 * j + 1][1] = r[3];
        }
    };

    stage(0);
    stage(1);
    for (int kt = 0; kt < KT; kt++) {
        if (kt < KT - 1) asm volatile("cp.async.wait_group 1;" ::: "memory");
        else             asm volatile("cp.async.wait_group 0;" ::: "memory");
        __syncthreads();
        if (kt + 2 < KT) stage(kt + 2);
        const uint32_t abase = sb + (kt % NST) * STAGE_BYTES;
        const uint32_t bbase = abase + BM * 128;
        load_frags(abase, bbase, 0, 0);
#pragma unroll
        for (int ks = 0; ks < BK / 16; ks++) {
            const int cur = ks & 1;
            if (ks < BK / 16 - 1) load_frags(abase, bbase, ks + 1, cur ^ 1);
#pragma unroll
            for (int mt = 0; mt < 4; mt++)
#pragma unroll
                for (int nt = 0; nt < 4; nt++)
                    mma16816(acc[mt][nt], af[cur][mt], bf[cur][nt]);
        }
    }

#pragma unroll
    for (int mt = 0; mt < 4; mt++) {
        const int row0 = bm + wm * 64 + mt * 16 + (lane >> 2);
#pragma unroll
        for (int nt = 0; nt < 4; nt++) {
            const int col = bn + wn * 32 + nt * 8 + (lane & 3) * 2;
            const float b0 = bias[col], b1 = bias[col + 1];
            *reinterpret_cast<uint32_t*>(Cout + (size_t)row0 * DIM + col) =
                pack_bf16(acc[mt][nt][0] + b0, acc[mt][nt][1] + b1);
            *reinterpret_cast<uint32_t*>(Cout + (size_t)(row0 + 8) * DIM + col) =
                pack_bf16(acc[mt][nt][2] + b0, acc[mt][nt][3] + b1);
        }
    }
}

// plain GEMM (O-projection)
__global__ __launch_bounds__(256, 2)
void gemm_kernel(const __nv_bfloat16* __restrict__ A,
                 const __nv_bfloat16* __restrict__ W,
                 const float* __restrict__ bias,
                 __nv_bfloat16* __restrict__ Cout) {
    gemm_body(blockIdx.x, blockIdx.y, A, W, bias, Cout);
}

// fused Q/K/V/gate GEMM: one 2048-CTA launch, segment from blockIdx.x>>3
__global__ __launch_bounds__(256, 2)
void gemm_qkvg_kernel(const __nv_bfloat16* __restrict__ hb,
                      const __nv_bfloat16* __restrict__ cb,
                      const __nv_bfloat16* __restrict__ w5,
                      const float* __restrict__ bq, const float* __restrict__ bk,
                      const float* __restrict__ bv, const float* __restrict__ bg,
                      __nv_bfloat16* __restrict__ q, __nv_bfloat16* __restrict__ k,
                      __nv_bfloat16* __restrict__ v, __nv_bfloat16* __restrict__ gate) {
    const int seg = blockIdx.x >> 3;       // 0:Q 1:K 2:V 3:gate
    const int bx  = blockIdx.x & 7;
    const __nv_bfloat16* A = (seg == 1 || seg == 2) ? cb : hb;
    const int widx = (seg == 3) ? 4 : seg; // gate uses Wg at slot 4
    const __nv_bfloat16* W = w5 + (size_t)widx * DIM * DIM;
    const float* bias = (seg == 0) ? bq : (seg == 1) ? bk : (seg == 2) ? bv : bg;
    __nv_bfloat16* out = (seg == 0) ? q : (seg == 1) ? k : (seg == 2) ? v : gate;
    gemm_body(bx, blockIdx.y, A, W, bias, out);
}

// ---------------- banded attention (round-2 verified) ----------------
__global__ __launch_bounds__(128)
void attn_kernel(const __nv_bfloat16* __restrict__ Q,
                 const __nv_bfloat16* __restrict__ K,
                 const __nv_bfloat16* __restrict__ V,
                 __nv_bfloat16* __restrict__ Out) {
    extern __shared__ char smem[];
    char* Ks = smem;             // 192 rows * 128B
    char* Vs = smem + 24576;     // 192 rows * 128B
    const int b = blockIdx.x >> 4, h = blockIdx.x & 15;
    const int qt = blockIdx.y;
    const int tid = threadIdx.x, lane = tid & 31, wid = tid >> 5;
    const int k0 = qt * 64 - 64;
    const size_t base = ((size_t)b * SEQ) * DIM + h * HDIM;

    for (int c = tid; c < 192 * 8; c += 128) {
        const int row = c >> 3, ch = c & 7;
        const int j = k0 + row;
        uint4 kv = make_uint4(0u, 0u, 0u, 0u), vv = make_uint4(0u, 0u, 0u, 0u);
        if (j >= 0 && j < SEQ) {
            kv = reinterpret_cast<const uint4*>(K + base + (size_t)j * DIM)[ch];
            vv = reinterpret_cast<const uint4*>(V + base + (size_t)j * DIM)[ch];
        }
        const int sw = ch ^ (row & 7);
        *reinterpret_cast<uint4*>(Ks + row * 128 + sw * 16) = kv;
        *reinterpret_cast<uint4*>(Vs + row * 128 + sw * 16) = vv;
    }
    __syncthreads();

    uint32_t qf[4][4];
    const int qr = qt * 64 + wid * 16 + (lane >> 2);
    {
        const __nv_bfloat16* q0 = Q + base + (size_t)qr * DIM;
        const __nv_bfloat16* q8 = Q + base + (size_t)(qr + 8) * DIM;
#pragma unroll
        for (int kt = 0; kt < 4; kt++) {
            const int c0 = kt * 16 + (lane & 3) * 2;
            qf[kt][0] = *reinterpret_cast<const uint32_t*>(q0 + c0);
            qf[kt][1] = *reinterpret_cast<const uint32_t*>(q8 + c0);
            qf[kt][2] = *reinterpret_cast<const uint32_t*>(q0 + c0 + 8);
            qf[kt][3] = *reinterpret_cast<const uint32_t*>(q8 + c0 + 8);
        }
    }

    float sc[24][4];
#pragma unroll
    for (int nt = 0; nt < 24; nt++)
#pragma unroll
        for (int i = 0; i < 4; i++) sc[nt][i] = 0.f;
#pragma unroll
    for (int kt = 0; kt < 4; kt++) {
#pragma unroll
        for (int nt = 0; nt < 24; nt++) {
            uint32_t kb[2];
            const int krow = nt * 8 + (lane & 7);
            const int ch = kt * 2 + ((lane >> 3) & 1);
            ldmx2(kb, (uint32_t)__cvta_generic_to_shared(Ks + krow * 128 + (ch ^ (krow & 7)) * 16));
            mma16816(sc[nt], qf[kt], kb);
        }
    }

    float mx0 = -1e30f, mx1 = -1e30f;
#pragma unroll
    for (int nt = 0; nt < 24; nt++) {
#pragma unroll
        for (int c = 0; c < 2; c++) {
            const int kj = k0 + nt * 8 + (lane & 3) * 2 + c;
            const bool inr = (kj >= 0) && (kj < SEQ);
            int d0 = qr - kj;     if (d0 < 0) d0 = -d0;
            int d1 = qr + 8 - kj; if (d1 < 0) d1 = -d1;
            const float s0 = (inr && d0 <= HALFWIN) ? sc[nt][c] * ATT_SCALE : -1e30f;
            const float s1 = (inr && d1 <= HALFWIN) ? sc[nt][c + 2] * ATT_SCALE : -1e30f;
            sc[nt][c] = s0; sc[nt][c + 2] = s1;
            mx0 = fmaxf(mx0, s0); mx1 = fmaxf(mx1, s1);
        }
    }
    mx0 = fmaxf(mx0, __shfl_xor_sync(0xffffffffu, mx0, 1));
    mx0 = fmaxf(mx0, __shfl_xor_sync(0xffffffffu, mx0, 2));
    mx1 = fmaxf(mx1, __shfl_xor_sync(0xffffffffu, mx1, 1));
    mx1 = fmaxf(mx1, __shfl_xor_sync(0xffffffffu, mx1, 2));
    float l0 = 0.f, l1 = 0.f;
#pragma unroll
    for (int nt = 0; nt < 24; nt++) {
#pragma unroll
        for (int c = 0; c < 2; c++) {
            const float p0 = __expf(sc[nt][c] - mx0);
            const float p1 = __expf(sc[nt][c + 2] - mx1);
            sc[nt][c] = p0; sc[nt][c + 2] = p1;
            l0 += p0; l1 += p1;
        }
    }
    l0 += __shfl_xor_sync(0xffffffffu, l0, 1);
    l0 += __shfl_xor_sync(0xffffffffu, l0, 2);
    l1 += __shfl_xor_sync(0xffffffffu, l1, 1);
    l1 += __shfl_xor_sync(0xffffffffu, l1, 2);

    float oacc[8][4];
#pragma unroll
    for (int dt = 0; dt < 8; dt++)
#pragma unroll
        for (int i = 0; i < 4; i++) oacc[dt][i] = 0.f;
#pragma unroll
    for (int jt = 0; jt < 12; jt++) {
        uint32_t pa[4];
        pa[0] = pack_bf16(sc[2 * jt][0], sc[2 * jt][1]);
        pa[1] = pack_bf16(sc[2 * jt][2], sc[2 * jt][3]);
        pa[2] = pack_bf16(sc[2 * jt + 1][0], sc[2 * jt + 1][1]);
        pa[3] = pack_bf16(sc[2 * jt + 1][2], sc[2 * jt + 1][3]);
        const int vrow = jt * 16 + (lane & 15);
#pragma unroll
        for (int dt = 0; dt < 8; dt++) {
            uint32_t vb[2];
            ldmx2t(vb, (uint32_t)__cvta_generic_to_shared(Vs + vrow * 128 + (dt ^ (vrow & 7)) * 16));
            mma16816(oacc[dt], pa, vb);
        }
    }

    const float i0 = 1.f / l0, i1 = 1.f / l1;
    __nv_bfloat16* ob = Out + base;
#pragma unroll
    for (int dt = 0; dt < 8; dt++) {
        const int col = dt * 8 + (lane & 3) * 2;
        *reinterpret_cast<uint32_t*>(ob + (size_t)qr * DIM + col) =
            pack_bf16(oacc[dt][0] * i0, oacc[dt][1] * i0);
        *reinterpret_cast<uint32_t*>(ob + (size_t)(qr + 8) * DIM + col) =
            pack_bf16(oacc[dt][2] * i1, oacc[dt][3] * i1);
    }
}

// ---------------- fused gate * attn, blend, LayerNorm (bf16 gate/yo) --------------
__global__ __launch_bounds__(256)
void final_kernel(const float* __restrict__ hid, const __nv_bfloat16* __restrict__ gate,
                  const __nv_bfloat16* __restrict__ yo, const float* __restrict__ gamma,
                  const float* __restrict__ beta, float* __restrict__ out) {
    const int row = blockIdx.x;
    const int tid = threadIdx.x;
    const size_t off = (size_t)row * DIM + tid * 4;
    const float4 hv = *reinterpret_cast<const float4*>(hid + off);
    const uint2 g2 = *reinterpret_cast<const uint2*>(gate + off);
    const uint2 y2 = *reinterpret_cast<const uint2*>(yo + off);
    const __nv_bfloat162 ga = *reinterpret_cast<const __nv_bfloat162*>(&g2.x);
    const __nv_bfloat162 gb = *reinterpret_cast<const __nv_bfloat162*>(&g2.y);
    const __nv_bfloat162 ya = *reinterpret_cast<const __nv_bfloat162*>(&y2.x);
    const __nv_bfloat162 yb = *reinterpret_cast<const __nv_bfloat162*>(&y2.y);
    const float gv[4] = {__bfloat162float(ga.x), __bfloat162float(ga.y),
                         __bfloat162float(gb.x), __bfloat162float(gb.y)};
    const float yv[4] = {__bfloat162float(ya.x), __bfloat162float(ya.y),
                         __bfloat162float(yb.x), __bfloat162float(yb.y)};
    const float hvv[4] = {hv.x, hv.y, hv.z, hv.w};
    float y[4];
#pragma unroll
    for (int i = 0; i < 4; i++)
        y[i] = 0.5f * hvv[i] + 0.5f * yv[i] / (1.f + __expf(-gv[i]));
    float s = y[0] + y[1] + y[2] + y[3];
    float s2 = y[0] * y[0] + y[1] * y[1] + y[2] * y[2] + y[3] * y[3];
#pragma unroll
    for (int o = 16; o > 0; o >>= 1) {
        s  += __shfl_xor_sync(0xffffffffu, s, o);
        s2 += __shfl_xor_sync(0xffffffffu, s2, o);
    }
    __shared__ float rs[8], rs2[8];
    if ((tid & 31) == 0) { rs[tid >> 5] = s; rs2[tid >> 5] = s2; }
    __syncthreads();
    float ts = 0.f, ts2 = 0.f;
#pragma unroll
    for (int w = 0; w < 8; w++) { ts += rs[w]; ts2 += rs2[w]; }
    const float mean = ts * (1.f / DIM);
    const float var = ts2 * (1.f / DIM) - mean * mean;
    const float rstd = rsqrtf(var + 1e-5f);
    const float4 gm = *reinterpret_cast<const float4*>(gamma + tid * 4);
    const float4 bt = *reinterpret_cast<const float4*>(beta + tid * 4);
    float4 o4;
    o4.x = (y[0] - mean) * rstd * gm.x + bt.x;
    o4.y = (y[1] - mean) * rstd * gm.y + bt.y;
    o4.z = (y[2] - mean) * rstd * gm.z + bt.z;
    o4.w = (y[3] - mean) * rstd * gm.w + bt.w;
    *reinterpret_cast<float4*>(out + off) = o4;
}

// ---------------- launch ----------------
extern "C" void kernel_launch(void* const* d_in, const int* in_sizes, int n_in,
                              void* d_out, int out_size) {
    (void)in_sizes; (void)n_in; (void)out_size;
    const float* hidden = (const float*)d_in[0];
    const float* cross  = (const float*)d_in[1];
    const float* Wq = (const float*)d_in[2];  const float* bq = (const float*)d_in[3];
    const float* Wk = (const float*)d_in[4];  const float* bk = (const float*)d_in[5];
    const float* Wv = (const float*)d_in[6];  const float* bv = (const float*)d_in[7];
    const float* Wo = (const float*)d_in[8];  const float* bo = (const float*)d_in[9];
    const float* Wg = (const float*)d_in[10]; const float* bg = (const float*)d_in[11];
    const float* gamma = (const float*)d_in[12];
    const float* beta  = (const float*)d_in[13];

    __nv_bfloat16 *hb, *cb, *w5, *q, *k, *v, *at, *gate, *yo;
    cudaGetSymbolAddress((void**)&hb, g_hb);
    cudaGetSymbolAddress((void**)&cb, g_cb);
    cudaGetSymbolAddress((void**)&w5, g_w5);
    cudaGetSymbolAddress((void**)&q,  g_q);
    cudaGetSymbolAddress((void**)&k,  g_k);
    cudaGetSymbolAddress((void**)&v,  g_v);
    cudaGetSymbolAddress((void**)&at, g_attn);
    cudaGetSymbolAddress((void**)&gate, g_gate);
    cudaGetSymbolAddress((void**)&yo,   g_yo);

    cudaFuncSetAttribute(gemm_kernel,
                         cudaFuncAttributeMaxDynamicSharedMemorySize, GEMM_SMEM);
    cudaFuncSetAttribute(gemm_qkvg_kernel,
                         cudaFuncAttributeMaxDynamicSharedMemorySize, GEMM_SMEM);

    const int nXDvec = MROWS * DIM / 4;
    cvt2_kernel<<<1024, 256>>>(hidden, hb, cross, cb, nXDvec);
    cvtw_kernel<<<dim3(128, 5), 256>>>(Wq, Wk, Wv, Wo, Wg);

    const __nv_bfloat16* wo = w5 + 3 * (size_t)DIM * DIM;

    // fused Q/K/V/gate: one 2048-CTA launch (4 segments x 8 n-tiles x 64 m-tiles)
    gemm_qkvg_kernel<<<dim3(32, 64), 256, GEMM_SMEM>>>(hb, cb, w5,
                                                       bq, bk, bv, bg,
                                                       q, k, v, gate);

    attn_kernel<<<dim3(BATCH * NH, SEQ / 64), 128, 49152>>>(q, k, v, at);

    gemm_kernel<<<dim3(8, 64), 256, GEMM_SMEM>>>(at, wo, bo, yo);

    final_kernel<<<MROWS, 256>>>(hidden, gate, yo, gamma, beta, (float*)d_out);
}

// round 10
// speedup vs baseline: 1.4975x; 1.0578x over previous
#include <cuda_runtime.h>
#include <cuda_bf16.h>
#include <cstdint>
#include <cstddef>

#define DEVI __device__ __forceinline__

namespace {
constexpr int BATCH = 16, SEQ = 512, DIM = 1024, NH = 16, HDIM = 64;
constexpr int MROWS = BATCH * SEQ;      // 8192
constexpr float ATT_SCALE = 0.125f;     // 1/sqrt(64)
constexpr int BM = 128, BN = 128, BK = 64;   // K-chunk = 64 bf16 = 128B row (XOR swizzle)
constexpr int KT = DIM / BK;                 // 16
constexpr int NST = 3;
constexpr int STAGE_BYTES = (BM + BN) * 128; // 32768 (A 16KB + B 16KB)
constexpr int GEMM_SMEM = NST * STAGE_BYTES + 256;
}

// ---------------- scratch (device globals; no allocation allowed) ----------------
__device__ __nv_bfloat16 g_hb[MROWS * DIM];
__device__ __nv_bfloat16 g_cb[MROWS * DIM];
__device__ __nv_bfloat16 g_w5[5 * DIM * DIM];   // Wq,Wk,Wv,Wo,Wg packed
__device__ __nv_bfloat16 g_q[MROWS * DIM];
__device__ __nv_bfloat16 g_k[MROWS * DIM];
__device__ __nv_bfloat16 g_v[MROWS * DIM];
__device__ __nv_bfloat16 g_attn[MROWS * DIM];
__device__ __nv_bfloat16 g_gate[MROWS * DIM];
__device__ __nv_bfloat16 g_yo[MROWS * DIM];

// ---------------- small helpers ----------------
DEVI uint32_t pack_bf16(float a, float b) {
    __nv_bfloat162 t;
    t.x = __float2bfloat16(a);
    t.y = __float2bfloat16(b);
    return *reinterpret_cast<uint32_t*>(&t);
}
DEVI void mma16816(float* c, const uint32_t* a, const uint32_t* b) {
    asm volatile(
        "mma.sync.aligned.m16n8k16.row.col.f32.bf16.bf16.f32 "
        "{%0,%1,%2,%3}, {%4,%5,%6,%7}, {%8,%9}, {%0,%1,%2,%3};"
        : "+f"(c[0]), "+f"(c[1]), "+f"(c[2]), "+f"(c[3])
        : "r"(a[0]), "r"(a[1]), "r"(a[2]), "r"(a[3]), "r"(b[0]), "r"(b[1]));
}
DEVI void ldmx4(uint32_t* r, uint32_t addr) {
    asm volatile("ldmatrix.sync.aligned.m8n8.x4.shared.b16 {%0,%1,%2,%3}, [%4];"
                 : "=r"(r[0]), "=r"(r[1]), "=r"(r[2]), "=r"(r[3]) : "r"(addr));
}
DEVI void ldmx2(uint32_t* r, uint32_t addr) {
    asm volatile("ldmatrix.sync.aligned.m8n8.x2.shared.b16 {%0,%1}, [%2];"
                 : "=r"(r[0]), "=r"(r[1]) : "r"(addr));
}
DEVI void ldmx2t(uint32_t* r, uint32_t addr) {
    asm volatile("ldmatrix.sync.aligned.m8n8.x2.trans.shared.b16 {%0,%1}, [%2];"
                 : "=r"(r[0]), "=r"(r[1]) : "r"(addr));
}
DEVI void cpasync16(uint32_t dst, const void* src) {
    asm volatile("cp.async.cg.shared.global [%0], [%1], 16;" :: "r"(dst), "l"(src));
}
DEVI void cpasync16z(uint32_t dst, const void* src, int srcsize) {
    asm volatile("cp.async.cg.shared.global [%0], [%1], 16, %2;"
                 :: "r"(dst), "l"(src), "r"(srcsize));
}

// ---------------- fused fp32 -> bf16 conversion (activations + 5 weights) --------
__global__ void cvt_all_kernel(const float* __restrict__ hidden, const float* __restrict__ cross,
                               const float* __restrict__ wq, const float* __restrict__ wk,
                               const float* __restrict__ wv, const float* __restrict__ wo,
                               const float* __restrict__ wg) {
    constexpr int ACT = MROWS * DIM / 4;   // 2097152 vec4
    constexpr int WV  = DIM * DIM / 4;     // 262144 vec4 (2^18)
    constexpr int TOT = 2 * ACT + 5 * WV;
    const int stride = gridDim.x * blockDim.x;
    for (int i = blockIdx.x * blockDim.x + threadIdx.x; i < TOT; i += stride) {
        const float* src;
        __nv_bfloat16* dst;
        int off;
        if (i < ACT)          { src = hidden; dst = g_hb; off = i; }
        else if (i < 2 * ACT) { src = cross;  dst = g_cb; off = i - ACT; }
        else {
            const int t = i - 2 * ACT;
            const int w = t >> 18;
            off = t & (WV - 1);
            src = (w == 0) ? wq : (w == 1) ? wk : (w == 2) ? wv : (w == 3) ? wo : wg;
            dst = g_w5 + (size_t)w * (DIM * DIM);
        }
        const int idx = off * 4;
        float4 f = *reinterpret_cast<const float4*>(src + idx);
        __nv_bfloat162 lo, hi;
        lo.x = __float2bfloat16(f.x); lo.y = __float2bfloat16(f.y);
        hi.x = __float2bfloat16(f.z); hi.y = __float2bfloat16(f.w);
        *reinterpret_cast<__nv_bfloat162*>(dst + idx)     = lo;
        *reinterpret_cast<__nv_bfloat162*>(dst + idx + 2) = hi;
    }
}

// ---------------- bf16 GEMM body: C[M,N] = A[M,K] @ W[N,K]^T + bias, bf16 out -----
DEVI void gemm_body(int bx, int by,
                    const __nv_bfloat16* __restrict__ A,
                    const __nv_bfloat16* __restrict__ W,
                    const float* __restrict__ bias,
                    __nv_bfloat16* __restrict__ Cout) {
    extern __shared__ char dsm[];
    const uint32_t sb = ((uint32_t)__cvta_generic_to_shared(dsm) + 127) & ~127u;
    const int tid  = threadIdx.x;
    const int lane = tid & 31, wid = tid >> 5;
    const int wm = wid >> 2, wn = wid & 3;
    const int bm = by * BM, bn = bx * BN;

    float acc[4][4][4];
#pragma unroll
    for (int mt = 0; mt < 4; mt++)
#pragma unroll
        for (int nt = 0; nt < 4; nt++)
#pragma unroll
            for (int i = 0; i < 4; i++) acc[mt][nt][i] = 0.f;

    auto stage = [&](int kt) {
        const uint32_t abase = sb + (kt % NST) * STAGE_BYTES;
        const uint32_t bbase = abase + BM * 128;
#pragma unroll
        for (int s = 0; s < 4; s++) {
            const int i = tid + s * 256;
            const int r = i >> 3, c = i & 7;
            cpasync16(abase + r * 128 + ((c ^ (r & 7)) * 16),
                      A + (size_t)(bm + r) * DIM + kt * BK + c * 8);
        }
#pragma unroll
        for (int s = 0; s < 4; s++) {
            const int i = tid + s * 256;
            const int r = i >> 3, c = i & 7;
            cpasync16(bbase + r * 128 + ((c ^ (r & 7)) * 16),
                      W + (size_t)(bn + r) * DIM + kt * BK + c * 8);
        }
        asm volatile("cp.async.commit_group;" ::: "memory");
    };

    uint32_t af[2][4][4], bf[2][4][2];
    auto load_frags = [&](uint32_t abase, uint32_t bbase, int ks, int p) {
#pragma unroll
        for (int mt = 0; mt < 4; mt++) {
            const int row = wm * 64 + mt * 16 + (lane & 15);
            const int c16 = ks * 2 + (lane >> 4);
            ldmx4(af[p][mt], abase + row * 128 + ((c16 ^ (row & 7)) * 16));
        }
#pragma unroll
        for (int j = 0; j < 2; j++) {
            const int row = wn * 32 + j * 16 + ((lane >> 4) & 1) * 8 + (lane & 7);
            const int c16 = ks * 2 + ((lane >> 3) & 1);
            uint32_t r[4];
            ldmx4(r, bbase + row * 128 + ((c16 ^ (row & 7)) * 16));
            bf[p][2 * j][0]     = r[0]; bf[p][2 * j][1]     = r[1];
            bf[p][2 * j + 1][0] = r[2]; bf[p][2 * j + 1][1] = r[3];
        }
    };

    stage(0);
    stage(1);
    for (int kt = 0; kt < KT; kt++) {
        if (kt < KT - 1) asm volatile("cp.async.wait_group 1;" ::: "memory");
        else             asm volatile("cp.async.wait_group 0;" ::: "memory");
        __syncthreads();
        if (kt + 2 < KT) stage(kt + 2);
        const uint32_t abase = sb + (kt % NST) * STAGE_BYTES;
        const uint32_t bbase = abase + BM * 128;
        load_frags(abase, bbase, 0, 0);
#pragma unroll
        for (int ks = 0; ks < BK / 16; ks++) {
            const int cur = ks & 1;
            if (ks < BK / 16 - 1) load_frags(abase, bbase, ks + 1, cur ^ 1);
#pragma unroll
            for (int mt = 0; mt < 4; mt++)
#pragma unroll
                for (int nt = 0; nt < 4; nt++)
                    mma16816(acc[mt][nt], af[cur][mt], bf[cur][nt]);
        }
    }

#pragma unroll
    for (int mt = 0; mt < 4; mt++) {
        const int row0 = bm + wm * 64 + mt * 16 + (lane >> 2);
#pragma unroll
        for (int nt = 0; nt < 4; nt++) {
            const int col = bn + wn * 32 + nt * 8 + (lane & 3) * 2;
            const float b0 = bias[col], b1 = bias[col + 1];
            *reinterpret_cast<uint32_t*>(Cout + (size_t)row0 * DIM + col) =
                pack_bf16(acc[mt][nt][0] + b0, acc[mt][nt][1] + b1);
            *reinterpret_cast<uint32_t*>(Cout + (size_t)(row0 + 8) * DIM + col) =
                pack_bf16(acc[mt][nt][2] + b0, acc[mt][nt][3] + b1);
        }
    }
}

// plain GEMM (O-projection)
__global__ __launch_bounds__(256, 2)
void gemm_kernel(const __nv_bfloat16* __restrict__ A,
                 const __nv_bfloat16* __restrict__ W,
                 const float* __restrict__ bias,
                 __nv_bfloat16* __restrict__ Cout) {
    gemm_body(blockIdx.x, blockIdx.y, A, W, bias, Cout);
}

// fused Q/K/V/gate GEMM: one 2048-CTA launch, segment from blockIdx.x>>3
__global__ __launch_bounds__(256, 2)
void gemm_qkvg_kernel(const __nv_bfloat16* __restrict__ hb,
                      const __nv_bfloat16* __restrict__ cb,
                      const __nv_bfloat16* __restrict__ w5,
                      const float* __restrict__ bq, const float* __restrict__ bk,
                      const float* __restrict__ bv, const float* __restrict__ bg,
                      __nv_bfloat16* __restrict__ q, __nv_bfloat16* __restrict__ k,
                      __nv_bfloat16* __restrict__ v, __nv_bfloat16* __restrict__ gate) {
    const int seg = blockIdx.x >> 3;       // 0:Q 1:K 2:V 3:gate
    const int bx  = blockIdx.x & 7;
    const __nv_bfloat16* A = (seg == 1 || seg == 2) ? cb : hb;
    const int widx = (seg == 3) ? 4 : seg; // gate uses Wg at slot 4
    const __nv_bfloat16* W = w5 + (size_t)widx * DIM * DIM;
    const float* bias = (seg == 0) ? bq : (seg == 1) ? bk : (seg == 2) ? bv : bg;
    __nv_bfloat16* out = (seg == 0) ? q : (seg == 1) ? k : (seg == 2) ? v : gate;
    gemm_body(bx, blockIdx.y, A, W, bias, out);
}

// ---------------- banded attention: reg-diet version ----------------
// block = (b*16+h, qtile of 64 queries), 128 threads. Band 192 keys in smem.
// P packed to bf16 at softmax time (sc dies -> pp), algebraic mask, cp.async zfill.
__global__ __launch_bounds__(128, 4)
void attn_kernel(const __nv_bfloat16* __restrict__ Q,
                 const __nv_bfloat16* __restrict__ K,
                 const __nv_bfloat16* __restrict__ V,
                 __nv_bfloat16* __restrict__ Out) {
    extern __shared__ char smem[];
    char* Ks = smem;             // 192 rows * 128B
    char* Vs = smem + 24576;     // 192 rows * 128B
    const int b = blockIdx.x >> 4, h = blockIdx.x & 15;
    const int qt = blockIdx.y;
    const int tid = threadIdx.x, lane = tid & 31, wid = tid >> 5;
    const int k0 = qt * 64 - 64;
    const size_t base = ((size_t)b * SEQ) * DIM + h * HDIM;

    // stage K,V band via cp.async (zfill for out-of-range rows)
    {
        const __nv_bfloat16* Kb = K + base;
        const __nv_bfloat16* Vb = V + base;
        for (int c = tid; c < 192 * 8; c += 128) {
            const int row = c >> 3, ch = c & 7;
            const int j = k0 + row;
            const bool ok = (j >= 0) && (j < SEQ);
            const int js = ok ? j : 0;
            const int sz = ok ? 16 : 0;
            const int sw = (ch ^ (row & 7)) * 16;
            cpasync16z((uint32_t)__cvta_generic_to_shared(Ks + row * 128 + sw),
                       reinterpret_cast<const char*>(Kb + (size_t)js * DIM) + ch * 16, sz);
            cpasync16z((uint32_t)__cvta_generic_to_shared(Vs + row * 128 + sw),
                       reinterpret_cast<const char*>(Vb + (size_t)js * DIM) + ch * 16, sz);
        }
        asm volatile("cp.async.commit_group;" ::: "memory");
    }

    // Q A-fragments directly from global
    uint32_t qf[4][4];
    const int wrow0 = wid * 16 + (lane >> 2);   // local query row (0..63)
    const int qr = qt * 64 + wrow0;
    {
        const __nv_bfloat16* q0 = Q + base + (size_t)qr * DIM;
        const __nv_bfloat16* q8 = Q + base + (size_t)(qr + 8) * DIM;
#pragma unroll
        for (int kt = 0; kt < 4; kt++) {
            const int c0 = kt * 16 + (lane & 3) * 2;
            qf[kt][0] = *reinterpret_cast<const uint32_t*>(q0 + c0);
            qf[kt][1] = *reinterpret_cast<const uint32_t*>(q8 + c0);
            qf[kt][2] = *reinterpret_cast<const uint32_t*>(q0 + c0 + 8);
            qf[kt][3] = *reinterpret_cast<const uint32_t*>(q8 + c0 + 8);
        }
    }
    asm volatile("cp.async.wait_group 0;" ::: "memory");
    __syncthreads();

    // S = Q @ K^T
    float sc[24][4];
#pragma unroll
    for (int nt = 0; nt < 24; nt++)
#pragma unroll
        for (int i = 0; i < 4; i++) sc[nt][i] = 0.f;
#pragma unroll
    for (int kt = 0; kt < 4; kt++) {
#pragma unroll
        for (int nt = 0; nt < 24; nt++) {
            uint32_t kb[2];
            const int krow = nt * 8 + (lane & 7);
            const int ch = kt * 2 + ((lane >> 3) & 1);
            ldmx2(kb, (uint32_t)__cvta_generic_to_shared(Ks + krow * 128 + (ch ^ (krow & 7)) * 16));
            mma16816(sc[nt], qf[kt], kb);
        }
    }

    // algebraic mask: valid iff wrow <= idx <= wrow+128 (band) and -k0 <= idx <= 511-k0
    const int lo0 = max(wrow0, -k0), hi0 = min(wrow0 + 128, 511 - k0);
    const int lo1 = max(wrow0 + 8, -k0), hi1 = min(wrow0 + 136, 511 - k0);
    const int colb = (lane & 3) * 2;
    float mx0 = -1e30f, mx1 = -1e30f;
#pragma unroll
    for (int nt = 0; nt < 24; nt++) {
#pragma unroll
        for (int c = 0; c < 2; c++) {
            const int idx = nt * 8 + colb + c;
            const float s0 = (idx >= lo0 && idx <= hi0) ? sc[nt][c] * ATT_SCALE : -1e30f;
            const float s1 = (idx >= lo1 && idx <= hi1) ? sc[nt][c + 2] * ATT_SCALE : -1e30f;
            sc[nt][c] = s0; sc[nt][c + 2] = s1;
            mx0 = fmaxf(mx0, s0); mx1 = fmaxf(mx1, s1);
        }
    }
    mx0 = fmaxf(mx0, __shfl_xor_sync(0xffffffffu, mx0, 1));
    mx0 = fmaxf(mx0, __shfl_xor_sync(0xffffffffu, mx0, 2));
    mx1 = fmaxf(mx1, __shfl_xor_sync(0xffffffffu, mx1, 1));
    mx1 = fmaxf(mx1, __shfl_xor_sync(0xffffffffu, mx1, 2));

    // exp + sum + pack to bf16 (sc dies into pp: 96 -> 48 regs)
    uint32_t pp[24][2];
    float l0 = 0.f, l1 = 0.f;
#pragma unroll
    for (int nt = 0; nt < 24; nt++) {
        const float p0 = __expf(sc[nt][0] - mx0);
        const float p1 = __expf(sc[nt][1] - mx0);
        const float p2 = __expf(sc[nt][2] - mx1);
        const float p3 = __expf(sc[nt][3] - mx1);
        l0 += p0 + p1; l1 += p2 + p3;
        pp[nt][0] = pack_bf16(p0, p1);
        pp[nt][1] = pack_bf16(p2, p3);
    }
    l0 += __shfl_xor_sync(0xffffffffu, l0, 1);
    l0 += __shfl_xor_sync(0xffffffffu, l0, 2);
    l1 += __shfl_xor_sync(0xffffffffu, l1, 1);
    l1 += __shfl_xor_sync(0xffffffffu, l1, 2);

    // O = P @ V
    float oacc[8][4];
#pragma unroll
    for (int dt = 0; dt < 8; dt++)
#pragma unroll
        for (int i = 0; i < 4; i++) oacc[dt][i] = 0.f;
#pragma unroll
    for (int jt = 0; jt < 12; jt++) {
        const uint32_t pa[4] = {pp[2 * jt][0], pp[2 * jt][1],
                                pp[2 * jt + 1][0], pp[2 * jt + 1][1]};
        const int vrow = jt * 16 + (lane & 15);
#pragma unroll
        for (int dt = 0; dt < 8; dt++) {
            uint32_t vb[2];
            ldmx2t(vb, (uint32_t)__cvta_generic_to_shared(Vs + vrow * 128 + (dt ^ (vrow & 7)) * 16));
            mma16816(oacc[dt], pa, vb);
        }
    }

    const float i0 = 1.f / l0, i1 = 1.f / l1;
    __nv_bfloat16* ob = Out + base;
#pragma unroll
    for (int dt = 0; dt < 8; dt++) {
        const int col = dt * 8 + (lane & 3) * 2;
        *reinterpret_cast<uint32_t*>(ob + (size_t)qr * DIM + col) =
            pack_bf16(oacc[dt][0] * i0, oacc[dt][1] * i0);
        *reinterpret_cast<uint32_t*>(ob + (size_t)(qr + 8) * DIM + col) =
            pack_bf16(oacc[dt][2] * i1, oacc[dt][3] * i1);
    }
}

// ---------------- fused gate * attn, blend, LayerNorm (bf16 gate/yo) --------------
__global__ __launch_bounds__(256)
void final_kernel(const float* __restrict__ hid, const __nv_bfloat16* __restrict__ gate,
                  const __nv_bfloat16* __restrict__ yo, const float* __restrict__ gamma,
                  const float* __restrict__ beta, float* __restrict__ out) {
    const int row = blockIdx.x;
    const int tid = threadIdx.x;
    const size_t off = (size_t)row * DIM + tid * 4;
    const float4 hv = *reinterpret_cast<const float4*>(hid + off);
    const uint2 g2 = *reinterpret_cast<const uint2*>(gate + off);
    const uint2 y2 = *reinterpret_cast<const uint2*>(yo + off);
    const __nv_bfloat162 ga = *reinterpret_cast<const __nv_bfloat162*>(&g2.x);
    const __nv_bfloat162 gb = *reinterpret_cast<const __nv_bfloat162*>(&g2.y);
    const __nv_bfloat162 ya = *reinterpret_cast<const __nv_bfloat162*>(&y2.x);
    const __nv_bfloat162 yb = *reinterpret_cast<const __nv_bfloat162*>(&y2.y);
    const float gv[4] = {__bfloat162float(ga.x), __bfloat162float(ga.y),
                         __bfloat162float(gb.x), __bfloat162float(gb.y)};
    const float yv[4] = {__bfloat162float(ya.x), __bfloat162float(ya.y),
                         __bfloat162float(yb.x), __bfloat162float(yb.y)};
    const float hvv[4] = {hv.x, hv.y, hv.z, hv.w};
    float y[4];
#pragma unroll
    for (int i = 0; i < 4; i++)
        y[i] = 0.5f * hvv[i] + 0.5f * yv[i] / (1.f + __expf(-gv[i]));
    float s = y[0] + y[1] + y[2] + y[3];
    float s2 = y[0] * y[0] + y[1] * y[1] + y[2] * y[2] + y[3] * y[3];
#pragma unroll
    for (int o = 16; o > 0; o >>= 1) {
        s  += __shfl_xor_sync(0xffffffffu, s, o);
        s2 += __shfl_xor_sync(0xffffffffu, s2, o);
    }
    __shared__ float rs[8], rs2[8];
    if ((tid & 31) == 0) { rs[tid >> 5] = s; rs2[tid >> 5] = s2; }
    __syncthreads();
    float ts = 0.f, ts2 = 0.f;
#pragma unroll
    for (int w = 0; w < 8; w++) { ts += rs[w]; ts2 += rs2[w]; }
    const float mean = ts * (1.f / DIM);
    const float var = ts2 * (1.f / DIM) - mean * mean;
    const float rstd = rsqrtf(var + 1e-5f);
    const float4 gm = *reinterpret_cast<const float4*>(gamma + tid * 4);
    const float4 bt = *reinterpret_cast<const float4*>(beta + tid * 4);
    float4 o4;
    o4.x = (y[0] - mean) * rstd * gm.x + bt.x;
    o4.y = (y[1] - mean) * rstd * gm.y + bt.y;
    o4.z = (y[2] - mean) * rstd * gm.z + bt.z;
    o4.w = (y[3] - mean) * rstd * gm.w + bt.w;
    *reinterpret_cast<float4*>(out + off) = o4;
}

// ---------------- launch ----------------
extern "C" void kernel_launch(void* const* d_in, const int* in_sizes, int n_in,
                              void* d_out, int out_size) {
    (void)in_sizes; (void)n_in; (void)out_size;
    const float* hidden = (const float*)d_in[0];
    const float* cross  = (const float*)d_in[1];
    const float* Wq = (const float*)d_in[2];  const float* bq = (const float*)d_in[3];
    const float* Wk = (const float*)d_in[4];  const float* bk = (const float*)d_in[5];
    const float* Wv = (const float*)d_in[6];  const float* bv = (const float*)d_in[7];
    const float* Wo = (const float*)d_in[8];  const float* bo = (const float*)d_in[9];
    const float* Wg = (const float*)d_in[10]; const float* bg = (const float*)d_in[11];
    const float* gamma = (const float*)d_in[12];
    const float* beta  = (const float*)d_in[13];

    __nv_bfloat16 *hb, *cb, *w5, *q, *k, *v, *at, *gate, *yo;
    cudaGetSymbolAddress((void**)&hb, g_hb);
    cudaGetSymbolAddress((void**)&cb, g_cb);
    cudaGetSymbolAddress((void**)&w5, g_w5);
    cudaGetSymbolAddress((void**)&q,  g_q);
    cudaGetSymbolAddress((void**)&k,  g_k);
    cudaGetSymbolAddress((void**)&v,  g_v);
    cudaGetSymbolAddress((void**)&at, g_attn);
    cudaGetSymbolAddress((void**)&gate, g_gate);
    cudaGetSymbolAddress((void**)&yo,   g_yo);

    cudaFuncSetAttribute(gemm_kernel,
                         cudaFuncAttributeMaxDynamicSharedMemorySize, GEMM_SMEM);
    cudaFuncSetAttribute(gemm_qkvg_kernel,
                         cudaFuncAttributeMaxDynamicSharedMemorySize, GEMM_SMEM);

    cvt_all_kernel<<<2752, 256>>>(hidden, cross, Wq, Wk, Wv, Wo, Wg);

    const __nv_bfloat16* wo = w5 + 3 * (size_t)DIM * DIM;

    gemm_qkvg_kernel<<<dim3(32, 64), 256, GEMM_SMEM>>>(hb, cb, w5,
                                                       bq, bk, bv, bg,
                                                       q, k, v, gate);

    attn_kernel<<<dim3(BATCH * NH, SEQ / 64), 128, 49152>>>(q, k, v, at);

    gemm_kernel<<<dim3(8, 64), 256, GEMM_SMEM>>>(at, wo, bo, yo);

    final_kernel<<<MROWS, 256>>>(hidden, gate, yo, gamma, beta, (float*)d_out);
}